// round 4
// baseline (speedup 1.0000x reference)
#include <cuda_runtime.h>
#include <cuda_bf16.h>
#include <math.h>

#define BB 1024
#define LL 32
#define DD 128
#define NNODE 50000
#define NNODE_PAD 50176   // 196 * 256

typedef unsigned long long ull;

// scratch between kernels
__device__ float g_hs[BB * DD];
__device__ __align__(16) __nv_bfloat16 g_embsplit[(size_t)NNODE_PAD * 384];
__device__ __align__(16) __nv_bfloat16 g_hssplit[BB * 384];

__device__ __forceinline__ float sigmoidf_(float x) { return 1.0f / (1.0f + expf(-x)); }

// ---- packed fp32x2 helpers (sm_100+: fma.rn.f32x2) ------------------------
__device__ __forceinline__ void fma2(ull& d, ull a, ull b) {
    asm("fma.rn.f32x2 %0, %1, %2, %0;" : "+l"(d) : "l"(a), "l"(b));
}
__device__ __forceinline__ ull pk2(float lo, float hi) {
    ull r; asm("mov.b64 %0, {%1, %2};" : "=l"(r) : "f"(lo), "f"(hi)); return r;
}
__device__ __forceinline__ float psum(ull a) {
    float lo, hi; asm("mov.b64 {%0, %1}, %2;" : "=f"(lo), "=f"(hi) : "l"(a));
    return lo + hi;
}

// acc{r,z,n}[l] += sum_k S[(l0+l)][k] * W[k][c{0,1,2}]   (16 l's, packed k-pairs)
__device__ __forceinline__ void acc3(ull* ar, ull* az, ull* an,
                                     const float* S,
                                     const float* __restrict__ W, int ldw,
                                     int c0, int c1, int c2, int l0)
{
    #pragma unroll 2
    for (int k = 0; k < DD; k += 4) {
        const float* wb = W + (size_t)k * ldw;
        ull w00 = pk2(wb[c0],         wb[ldw + c0]);
        ull w01 = pk2(wb[2*ldw + c0], wb[3*ldw + c0]);
        ull w10 = pk2(wb[c1],         wb[ldw + c1]);
        ull w11 = pk2(wb[2*ldw + c1], wb[3*ldw + c1]);
        ull w20 = pk2(wb[c2],         wb[ldw + c2]);
        ull w21 = pk2(wb[2*ldw + c2], wb[3*ldw + c2]);
        #pragma unroll
        for (int l = 0; l < 16; l++) {
            ulonglong2 s = *(const ulonglong2*)&S[(l0 + l) * DD + k];
            fma2(ar[l], s.x, w00); fma2(ar[l], s.y, w01);
            fma2(az[l], s.x, w10); fma2(az[l], s.y, w11);
            fma2(an[l], s.x, w20); fma2(an[l], s.y, w21);
        }
    }
}

__device__ __forceinline__ void acc2w(ull* a0, ull* a1, const float* S,
                                      const float* __restrict__ W0,
                                      const float* __restrict__ W1, int c, int l0)
{
    #pragma unroll 2
    for (int k = 0; k < DD; k += 4) {
        ull w00 = pk2(W0[k*DD + c],     W0[(k+1)*DD + c]);
        ull w01 = pk2(W0[(k+2)*DD + c], W0[(k+3)*DD + c]);
        ull w10 = pk2(W1[k*DD + c],     W1[(k+1)*DD + c]);
        ull w11 = pk2(W1[(k+2)*DD + c], W1[(k+3)*DD + c]);
        #pragma unroll
        for (int l = 0; l < 16; l++) {
            ulonglong2 s = *(const ulonglong2*)&S[(l0 + l) * DD + k];
            fma2(a0[l], s.x, w00); fma2(a0[l], s.y, w01);
            fma2(a1[l], s.x, w10); fma2(a1[l], s.y, w11);
        }
    }
}

__device__ __forceinline__ void acc1(ull* a0, const float* S,
                                     const float* __restrict__ W, int ldw, int c)
{
    #pragma unroll 2
    for (int k = 0; k < DD; k += 4) {
        ull w0 = pk2(W[k*ldw + c],     W[(k+1)*ldw + c]);
        ull w1 = pk2(W[(k+2)*ldw + c], W[(k+3)*ldw + c]);
        #pragma unroll
        for (int l = 0; l < LL; l++) {
            ulonglong2 s = *(const ulonglong2*)&S[l * DD + k];
            fma2(a0[l], s.x, w0); fma2(a0[l], s.y, w1);
        }
    }
}

// ---------------------------------------------------------------------------
// Kernel 1: everything up to h_s (unchanged from round 3).
// ---------------------------------------------------------------------------
__global__ void __launch_bounds__(128) session_kernel(
    const int* __restrict__ items, const float* __restrict__ A_in,
    const float* __restrict__ A_out, const float* __restrict__ inter,
    const int* __restrict__ seq_len, const float* __restrict__ emb,
    const float* __restrict__ W_in, const float* __restrict__ b_in,
    const float* __restrict__ W_out, const float* __restrict__ b_out,
    const float* __restrict__ W_a, const float* __restrict__ U_h,
    const float* __restrict__ b_gru,
    const float* __restrict__ Wi, const float* __restrict__ bi,
    const float* __restrict__ Wh, const float* __restrict__ bh,
    const float* __restrict__ W1, const float* __restrict__ b1,
    const float* __restrict__ W2, const float* __restrict__ b2,
    const float* __restrict__ wq, const float* __restrict__ bq,
    const float* __restrict__ W3, const float* __restrict__ b3)
{
    extern __shared__ float sm[];
    float* H      = sm;
    float* T1     = sm + 4096;
    float* T2     = sm + 8192;
    float* T3     = sm + 12288;
    float* T4     = sm + 16384;
    float* sAin   = sm + 20480;
    float* sAout  = sm + 21504;
    float* sv     = sm + 22528;
    float* ssg    = sm + 22656;
    float* salpha = sm + 22784;
    float* sred   = sm + 22816;

    const int b = blockIdx.x;
    const int d = threadIdx.x;
    const int warp = d >> 5, lane = d & 31;

    #pragma unroll 4
    for (int l = 0; l < LL; l++) {
        int idx = items[b * LL + l];
        H[l * DD + d] = emb[idx * DD + d];
    }
    for (int i = d; i < LL * LL; i += DD) {
        sAin[i]  = A_in[b * LL * LL + i];
        sAout[i] = A_out[b * LL * LL + i];
    }
    __syncthreads();

    for (int h = 0; h < 2; h++) {
        const int l0 = h * 16;
        ull a0[16], a1[16];
        #pragma unroll
        for (int l = 0; l < 16; l++) { a0[l] = 0ull; a1[l] = 0ull; }
        acc2w(a0, a1, H, W_in, W_out, d, l0);
        float bv0 = b_in[d], bv1 = b_out[d];
        #pragma unroll
        for (int l = 0; l < 16; l++) {
            T1[(l0 + l) * DD + d] = psum(a0[l]) + bv0;
            T2[(l0 + l) * DD + d] = psum(a1[l]) + bv1;
        }
    }

    {
        float acc[LL];
        #pragma unroll
        for (int l = 0; l < LL; l++) acc[l] = 0.0f;
        #pragma unroll 4
        for (int m = 0; m < LL; m++) {
            float tv = T1[m * DD + d];
            #pragma unroll
            for (int l = 0; l < LL; l++) acc[l] = fmaf(sAin[l * LL + m], tv, acc[l]);
        }
        #pragma unroll
        for (int l = 0; l < LL; l++) T3[l * DD + d] = acc[l];

        #pragma unroll
        for (int l = 0; l < LL; l++) acc[l] = 0.0f;
        #pragma unroll 4
        for (int m = 0; m < LL; m++) {
            float tv = T2[m * DD + d];
            #pragma unroll
            for (int l = 0; l < LL; l++) acc[l] = fmaf(sAout[l * LL + m], tv, acc[l]);
        }
        #pragma unroll
        for (int l = 0; l < LL; l++) T4[l * DD + d] = acc[l];
    }
    __syncthreads();

    for (int h = 0; h < 2; h++) {
        const int l0 = h * 16;
        ull ar[16], az[16], an[16];
        #pragma unroll
        for (int l = 0; l < 16; l++) { ar[l] = az[l] = an[l] = 0ull; }
        acc3(ar, az, an, T3, W_a,              3*DD, d, DD + d, 2*DD + d, l0);
        acc3(ar, az, an, T4, W_a + DD * 3*DD,  3*DD, d, DD + d, 2*DD + d, l0);
        float inv[16];
        {
            float br = b_gru[d], bz = b_gru[DD + d], bn = b_gru[2*DD + d];
            #pragma unroll
            for (int l = 0; l < 16; l++) {
                T1[(l0 + l) * DD + d] = psum(ar[l]) + br;
                T2[(l0 + l) * DD + d] = psum(az[l]) + bz;
                inv[l] = psum(an[l]) + bn;
            }
        }
        #pragma unroll
        for (int l = 0; l < 16; l++) { ar[l] = az[l] = an[l] = 0ull; }
        acc3(ar, az, an, H, U_h, 3*DD, d, DD + d, 2*DD + d, l0);
        #pragma unroll
        for (int l = 0; l < 16; l++) {
            float r = sigmoidf_(T1[(l0 + l) * DD + d] + psum(ar[l]));
            float z = sigmoidf_(T2[(l0 + l) * DD + d] + psum(az[l]));
            float n = tanhf(inv[l] + r * psum(an[l]));
            T1[(l0 + l) * DD + d] = (1.0f - z) * n + z * H[(l0 + l) * DD + d];
        }
    }
    __syncthreads();
    #pragma unroll 4
    for (int l = 0; l < LL; l++) {
        T3[l * DD + d] = T1[l * DD + d];
        H[l * DD + d]  = inter[(b * LL + l) * DD + d];
    }
    __syncthreads();

    for (int h = 0; h < 2; h++) {
        const int l0 = h * 16;
        ull ar[16], az[16], an[16];
        #pragma unroll
        for (int l = 0; l < 16; l++) { ar[l] = az[l] = an[l] = 0ull; }
        acc3(ar, az, an, T3, Wi, 3*DD, d, DD + d, 2*DD + d, l0);
        float inv[16];
        {
            float br = bi[d], bz = bi[DD + d], bn = bi[2*DD + d];
            #pragma unroll
            for (int l = 0; l < 16; l++) {
                T1[(l0 + l) * DD + d] = psum(ar[l]) + br;
                T2[(l0 + l) * DD + d] = psum(az[l]) + bz;
                inv[l] = psum(an[l]) + bn;
            }
        }
        #pragma unroll
        for (int l = 0; l < 16; l++) { ar[l] = az[l] = an[l] = 0ull; }
        acc3(ar, az, an, H, Wh, 3*DD, d, DD + d, 2*DD + d, l0);
        {
            float br = bh[d], bz = bh[DD + d], bn = bh[2*DD + d];
            #pragma unroll
            for (int l = 0; l < 16; l++) {
                float r = sigmoidf_(T1[(l0 + l) * DD + d] + psum(ar[l]) + br);
                float z = sigmoidf_(T2[(l0 + l) * DD + d] + psum(az[l]) + bz);
                float n = tanhf(inv[l] + r * (psum(an[l]) + bn));
                T4[(l0 + l) * DD + d] = (1.0f - z) * n + z * H[(l0 + l) * DD + d];
            }
        }
    }

    const int slen = seq_len[b];
    sv[d] = T4[(slen - 1) * DD + d];
    __syncthreads();

    float q1 = b1[d];
    #pragma unroll 4
    for (int k = 0; k < DD; k++) q1 = fmaf(sv[k], W1[k * DD + d], q1);

    float acc[LL];
    {
        ull aw[LL];
        #pragma unroll
        for (int l = 0; l < LL; l++) aw[l] = 0ull;
        acc1(aw, T4, W2, DD, d);
        float bv = b2[d];
        #pragma unroll
        for (int l = 0; l < LL; l++) acc[l] = psum(aw[l]) + bv;
    }
    {
        float wqd = wq[d];
        #pragma unroll
        for (int l = 0; l < LL; l++) {
            float g = sigmoidf_(q1 + acc[l]) * wqd;
            #pragma unroll
            for (int off = 16; off > 0; off >>= 1)
                g += __shfl_xor_sync(0xffffffffu, g, off);
            if (lane == 0) sred[l * 4 + warp] = g;
        }
        __syncthreads();
        if (d < LL) {
            float a_ = sred[d * 4] + sred[d * 4 + 1] + sred[d * 4 + 2] + sred[d * 4 + 3] + bq[0];
            salpha[d] = (d < slen) ? a_ : 0.0f;
        }
        __syncthreads();
    }
    {
        float sg = 0.0f;
        #pragma unroll
        for (int l = 0; l < LL; l++) sg = fmaf(salpha[l], T4[l * DD + d], sg);
        ssg[d] = sg;
    }
    __syncthreads();
    {
        float hs = b3[d];
        #pragma unroll 4
        for (int k = 0; k < DD; k++) hs = fmaf(sv[k], W3[k * DD + d], hs);
        #pragma unroll 4
        for (int k = 0; k < DD; k++) hs = fmaf(ssg[k], W3[(DD + k) * DD + d], hs);
        g_hs[b * DD + d] = hs;
    }
}

// ---------------------------------------------------------------------------
// Split-bf16 conversion kernels.
// B' row layout (384): [hi(0:128) | lo(128:256) | hi(256:384)]
// A' row layout (384): [hi        | hi          | lo          ]
// => A'.B' = Ahi.Bhi + Ahi.Blo + Alo.Bhi
// ---------------------------------------------------------------------------
__global__ void __launch_bounds__(256) split_emb_kernel(const float* __restrict__ emb)
{
    int i = blockIdx.x * 256 + threadIdx.x;       // over NNODE_PAD*128
    int n = i >> 7, d = i & 127;
    float x = (n < NNODE) ? emb[(size_t)n * DD + d] : 0.0f;
    __nv_bfloat16 hi = __float2bfloat16(x);
    __nv_bfloat16 lo = __float2bfloat16(x - __bfloat162float(hi));
    __nv_bfloat16* row = g_embsplit + (size_t)n * 384;
    row[d] = hi; row[128 + d] = lo; row[256 + d] = hi;
}

__global__ void __launch_bounds__(256) split_hs_kernel()
{
    int i = blockIdx.x * 256 + threadIdx.x;       // over BB*128
    int m = i >> 7, d = i & 127;
    float x = g_hs[m * DD + d];
    __nv_bfloat16 hi = __float2bfloat16(x);
    __nv_bfloat16 lo = __float2bfloat16(x - __bfloat162float(hi));
    __nv_bfloat16* row = g_hssplit + (size_t)m * 384;
    row[d] = hi; row[128 + d] = hi; row[256 + d] = lo;
}

// ---------------------------------------------------------------------------
// Kernel 2: scores = A' @ B'^T via mma.sync bf16 (K=384).
// CTA 128x256, 8 warps of 64x64, cp.async double-buffered KC=64 chunks.
// smem rows padded to 72 bf16 (144B) -> conflict-free ldmatrix/cp.async.
// ---------------------------------------------------------------------------
#define GK 384
#define KC 64
#define GBM 128
#define GBN 256
#define SROW 72                     // bf16 per smem row (144 B)
#define ABUF_B (GBM * SROW * 2)     // 18432 B
#define BBUF_B (GBN * SROW * 2)     // 36864 B
#define STAGE_B (ABUF_B + BBUF_B)   // 55296 B

__device__ __forceinline__ void cp16(unsigned saddr, const void* gptr) {
    asm volatile("cp.async.cg.shared.global [%0], [%1], 16;\n"
                 :: "r"(saddr), "l"(gptr));
}
__device__ __forceinline__ void cp_commit() {
    asm volatile("cp.async.commit_group;\n");
}
template<int N> __device__ __forceinline__ void cp_wait() {
    asm volatile("cp.async.wait_group %0;\n" :: "n"(N));
}
__device__ __forceinline__ void ldm4(unsigned* r, unsigned saddr) {
    asm volatile("ldmatrix.sync.aligned.m8n8.x4.shared.b16 {%0,%1,%2,%3}, [%4];"
                 : "=r"(r[0]), "=r"(r[1]), "=r"(r[2]), "=r"(r[3]) : "r"(saddr));
}
__device__ __forceinline__ void mma16816(float* c, const unsigned* a, const unsigned* b) {
    asm volatile("mma.sync.aligned.m16n8k16.row.col.f32.bf16.bf16.f32 "
                 "{%0,%1,%2,%3}, {%4,%5,%6,%7}, {%8,%9}, {%0,%1,%2,%3};"
                 : "+f"(c[0]), "+f"(c[1]), "+f"(c[2]), "+f"(c[3])
                 : "r"(a[0]), "r"(a[1]), "r"(a[2]), "r"(a[3]),
                   "r"(b[0]), "r"(b[1]));
}

__global__ void __launch_bounds__(256) scores_mma_kernel(float* __restrict__ out)
{
    extern __shared__ char smraw[];
    const unsigned sbase = (unsigned)__cvta_generic_to_shared(smraw);

    const int tid = threadIdx.x, lane = tid & 31, w = tid >> 5;
    const int wm = w & 1, wn = w >> 1;            // 2 M-warps x 4 N-warps
    const int bm0 = blockIdx.y * GBM;
    const int n0  = blockIdx.x * GBN;

    const __nv_bfloat16* Ag0 = g_hssplit + (size_t)bm0 * GK;
    const __nv_bfloat16* Bg0 = g_embsplit + (size_t)n0 * GK;

    // per-thread load coords (16B chunks)
    const int lr = tid >> 3, lc8 = tid & 7;

    // stage loader
    auto load_stage = [&](int s, int buf) {
        unsigned ab = sbase + buf * STAGE_B;
        unsigned bb = ab + ABUF_B;
        const __nv_bfloat16* Ag = Ag0 + s * KC;
        const __nv_bfloat16* Bg = Bg0 + s * KC;
        #pragma unroll
        for (int i = 0; i < 4; i++) {             // A: 128 rows
            int r = lr + i * 32;
            cp16(ab + r * 144 + lc8 * 16, Ag + (size_t)r * GK + lc8 * 8);
        }
        #pragma unroll
        for (int i = 0; i < 8; i++) {             // B: 256 rows
            int r = lr + i * 32;
            cp16(bb + r * 144 + lc8 * 16, Bg + (size_t)r * GK + lc8 * 8);
        }
    };

    float acc[4][8][4];
    #pragma unroll
    for (int mi = 0; mi < 4; mi++)
        #pragma unroll
        for (int j = 0; j < 8; j++)
            #pragma unroll
            for (int q = 0; q < 4; q++) acc[mi][j][q] = 0.0f;

    // ldmatrix per-thread invariants
    const int a_r  = wm * 64 + (lane & 15);
    const int a_cb = ((lane >> 4) & 1) * 16;
    const int b_r  = wn * 64 + ((lane >> 4) & 1) * 8 + (lane & 7);
    const int b_cb = ((lane >> 3) & 1) * 16;

    load_stage(0, 0);
    cp_commit();

    #pragma unroll
    for (int s = 0; s < GK / KC; s++) {
        if (s < GK / KC - 1) {
            load_stage(s + 1, (s + 1) & 1);
            cp_commit();
            cp_wait<1>();
        } else {
            cp_wait<0>();
        }
        __syncthreads();

        unsigned ab = sbase + (s & 1) * STAGE_B;
        unsigned bb = ab + ABUF_B;

        #pragma unroll
        for (int kk = 0; kk < KC / 16; kk++) {
            unsigned bfr[4][4];
            #pragma unroll
            for (int ni = 0; ni < 4; ni++)
                ldm4(bfr[ni], bb + (b_r + ni * 16) * 144 + kk * 32 + b_cb);
            #pragma unroll
            for (int mi = 0; mi < 4; mi++) {
                unsigned af[4];
                ldm4(af, ab + (a_r + mi * 16) * 144 + kk * 32 + a_cb);
                #pragma unroll
                for (int ni = 0; ni < 4; ni++) {
                    mma16816(acc[mi][2 * ni],     af, &bfr[ni][0]);
                    mma16816(acc[mi][2 * ni + 1], af, &bfr[ni][2]);
                }
            }
        }
        __syncthreads();
    }

    // epilogue
    const int r0 = bm0 + wm * 64 + (lane >> 2);
    const int c0 = n0 + wn * 64 + (lane & 3) * 2;
    #pragma unroll
    for (int mi = 0; mi < 4; mi++) {
        int row = r0 + mi * 16;
        #pragma unroll
        for (int j = 0; j < 8; j++) {
            int n = c0 + j * 8;
            if (n < NNODE) {
                *(float2*)&out[(size_t)row * NNODE + n] =
                    make_float2(acc[mi][j][0], acc[mi][j][1]);
                *(float2*)&out[(size_t)(row + 8) * NNODE + n] =
                    make_float2(acc[mi][j][2], acc[mi][j][3]);
            }
        }
    }
}

// ---------------------------------------------------------------------------
extern "C" void kernel_launch(void* const* d_in, const int* in_sizes, int n_in,
                              void* d_out, int out_size)
{
    (void)in_sizes; (void)n_in; (void)out_size;
    const int*   items   = (const int*)d_in[0];
    const float* A_in    = (const float*)d_in[1];
    const float* A_out   = (const float*)d_in[2];
    const float* inter   = (const float*)d_in[3];
    const int*   seq_len = (const int*)d_in[4];
    const float* emb     = (const float*)d_in[5];
    const float* W_in    = (const float*)d_in[6];
    const float* b_in    = (const float*)d_in[7];
    const float* W_out   = (const float*)d_in[8];
    const float* b_out   = (const float*)d_in[9];
    const float* W_a     = (const float*)d_in[10];
    const float* U_h     = (const float*)d_in[11];
    const float* b_gru   = (const float*)d_in[12];
    const float* Wi      = (const float*)d_in[13];
    const float* bi      = (const float*)d_in[14];
    const float* Wh      = (const float*)d_in[15];
    const float* bh      = (const float*)d_in[16];
    const float* W1      = (const float*)d_in[17];
    const float* b1      = (const float*)d_in[18];
    const float* W2      = (const float*)d_in[19];
    const float* b2      = (const float*)d_in[20];
    const float* wq      = (const float*)d_in[21];
    const float* bq      = (const float*)d_in[22];
    const float* W3      = (const float*)d_in[23];
    const float* b3      = (const float*)d_in[24];
    float* out = (float*)d_out;

    const int smem_session = 22944 * 4;          // 91,776 B
    const int smem_gemm    = 2 * STAGE_B;        // 110,592 B
    cudaFuncSetAttribute(session_kernel, cudaFuncAttributeMaxDynamicSharedMemorySize,
                         smem_session);
    cudaFuncSetAttribute(scores_mma_kernel, cudaFuncAttributeMaxDynamicSharedMemorySize,
                         smem_gemm);

    // emb split (independent of session, tiny)
    split_emb_kernel<<<(NNODE_PAD * 128) / 256, 256>>>(emb);

    session_kernel<<<BB, 128, smem_session>>>(
        items, A_in, A_out, inter, seq_len, emb,
        W_in, b_in, W_out, b_out, W_a, U_h, b_gru,
        Wi, bi, Wh, bh, W1, b1, W2, b2, wq, bq, W3, b3);

    split_hs_kernel<<<(BB * 128) / 256, 256>>>();

    dim3 grid(NNODE_PAD / GBN, BB / GBM);        // 196 x 8
    scores_mma_kernel<<<grid, 256, smem_gemm>>>(out);
}

// round 7
// speedup vs baseline: 1.3428x; 1.3428x over previous
#include <cuda_runtime.h>
#include <cuda_bf16.h>
#include <math.h>

#define BB 1024
#define LL 32
#define DD 128
#define NNODE 50000

typedef unsigned long long ull;

// scratch between kernels
__device__ float g_hs[BB * DD];

// k4-packed weights: element [k4*cols + c] = (W[4k4][c], W[4k4+1][c], W[4k4+2][c], W[4k4+3][c])
__device__ __align__(16) float4 g_Wa_p[64 * 384];   // W_a  [256,384]
__device__ __align__(16) float4 g_Uh_p[32 * 384];   // U_h  [128,384]
__device__ __align__(16) float4 g_Wi_p[32 * 384];   // Wi   [128,384]
__device__ __align__(16) float4 g_Wh_p[32 * 384];   // Wh   [128,384]
__device__ __align__(16) float4 g_Win_p[32 * 128];  // W_in [128,128]
__device__ __align__(16) float4 g_Wout_p[32 * 128]; // W_out[128,128]
__device__ __align__(16) float4 g_W2_p[32 * 128];   // W2   [128,128]

__device__ __forceinline__ float sigmoidf_(float x) { return 1.0f / (1.0f + expf(-x)); }

// ---- packed fp32x2 helpers (sm_100+: fma.rn.f32x2) ------------------------
__device__ __forceinline__ void fma2(ull& d, ull a, ull b) {
    asm("fma.rn.f32x2 %0, %1, %2, %0;" : "+l"(d) : "l"(a), "l"(b));
}
__device__ __forceinline__ float psum(ull a) {
    float lo, hi; asm("mov.b64 {%0, %1}, %2;" : "=f"(lo), "=f"(hi) : "l"(a));
    return lo + hi;
}

// ---------------------------------------------------------------------------
// Weight pack kernel (runs every call, ~1MB traffic)
// ---------------------------------------------------------------------------
__device__ __forceinline__ void pack_one(float4* dst, const float* src, int cols, int i)
{
    int k4 = i / cols, c = i - k4 * cols;
    const float* s = src + (size_t)(k4 * 4) * cols + c;
    dst[i] = make_float4(s[0], s[cols], s[2 * cols], s[3 * cols]);
}

__global__ void __launch_bounds__(256) pack_weights_kernel(
    const float* __restrict__ W_a, const float* __restrict__ U_h,
    const float* __restrict__ Wi, const float* __restrict__ Wh,
    const float* __restrict__ W_in, const float* __restrict__ W_out,
    const float* __restrict__ W2)
{
    int idx = blockIdx.x * 256 + threadIdx.x;
    if (idx < 24576)      pack_one(g_Wa_p,  W_a,  384, idx);
    else if (idx < 36864) pack_one(g_Uh_p,  U_h,  384, idx - 24576);
    else if (idx < 49152) pack_one(g_Wi_p,  Wi,   384, idx - 36864);
    else if (idx < 61440) pack_one(g_Wh_p,  Wh,   384, idx - 49152);
    else if (idx < 65536) pack_one(g_Win_p, W_in, 128, idx - 61440);
    else if (idx < 69632) pack_one(g_Wout_p,W_out,128, idx - 65536);
    else if (idx < 73728) pack_one(g_W2_p,  W2,   128, idx - 69632);
}

// ---------------------------------------------------------------------------
// packed accumulate helpers
// ---------------------------------------------------------------------------
// acc{r,z,n}[l] += sum_k S[(l0+l)][k] * W[k][{d,128+d,256+d}]  (packed W, 384 cols)
__device__ __forceinline__ void acc3p(ull* ar, ull* az, ull* an,
                                      const float* S, const float4* __restrict__ Wp,
                                      int d, int l0)
{
    const ulonglong2* W = (const ulonglong2*)Wp;
    #pragma unroll 2
    for (int k4 = 0; k4 < 32; k4++) {
        const ulonglong2* wb = W + k4 * 384;
        ulonglong2 w0 = wb[d], w1 = wb[128 + d], w2 = wb[256 + d];
        #pragma unroll
        for (int l = 0; l < 16; l++) {
            ulonglong2 s = *(const ulonglong2*)&S[(l0 + l) * DD + k4 * 4];
            fma2(ar[l], s.x, w0.x); fma2(ar[l], s.y, w0.y);
            fma2(az[l], s.x, w1.x); fma2(az[l], s.y, w1.y);
            fma2(an[l], s.x, w2.x); fma2(an[l], s.y, w2.y);
        }
    }
}

// a0[l] += S@W0[:,d], a1[l] += S@W1[:,d]  (packed, 128 cols)
__device__ __forceinline__ void acc2wp(ull* a0, ull* a1, const float* S,
                                       const float4* __restrict__ W0p,
                                       const float4* __restrict__ W1p, int d, int l0)
{
    const ulonglong2* W0 = (const ulonglong2*)W0p;
    const ulonglong2* W1 = (const ulonglong2*)W1p;
    #pragma unroll 2
    for (int k4 = 0; k4 < 32; k4++) {
        ulonglong2 w0 = W0[k4 * 128 + d];
        ulonglong2 w1 = W1[k4 * 128 + d];
        #pragma unroll
        for (int l = 0; l < 16; l++) {
            ulonglong2 s = *(const ulonglong2*)&S[(l0 + l) * DD + k4 * 4];
            fma2(a0[l], s.x, w0.x); fma2(a0[l], s.y, w0.y);
            fma2(a1[l], s.x, w1.x); fma2(a1[l], s.y, w1.y);
        }
    }
}

// a0[l] += S@W[:,d]  (packed, 128 cols, 32 l's)
__device__ __forceinline__ void acc1p(ull* a0, const float* S,
                                      const float4* __restrict__ Wp, int d)
{
    const ulonglong2* W = (const ulonglong2*)Wp;
    #pragma unroll 2
    for (int k4 = 0; k4 < 32; k4++) {
        ulonglong2 w = W[k4 * 128 + d];
        #pragma unroll
        for (int l = 0; l < LL; l++) {
            ulonglong2 s = *(const ulonglong2*)&S[l * DD + k4 * 4];
            fma2(a0[l], s.x, w.x); fma2(a0[l], s.y, w.y);
        }
    }
}

// ---------------------------------------------------------------------------
// Kernel 1: everything up to h_s.  One CTA per batch element, 128 threads.
// ---------------------------------------------------------------------------
__global__ void __launch_bounds__(128) session_kernel(
    const int* __restrict__ items, const float* __restrict__ A_in,
    const float* __restrict__ A_out, const float* __restrict__ inter,
    const int* __restrict__ seq_len, const float* __restrict__ emb,
    const float* __restrict__ b_in, const float* __restrict__ b_out,
    const float* __restrict__ b_gru,
    const float* __restrict__ bi, const float* __restrict__ bh,
    const float* __restrict__ W1, const float* __restrict__ b1,
    const float* __restrict__ b2,
    const float* __restrict__ wq, const float* __restrict__ bq,
    const float* __restrict__ W3, const float* __restrict__ b3)
{
    extern __shared__ float sm[];
    float* H      = sm;
    float* T1     = sm + 4096;
    float* T2     = sm + 8192;
    float* T3     = sm + 12288;
    float* T4     = sm + 16384;
    float* sAin   = sm + 20480;
    float* sAout  = sm + 21504;
    float* sv     = sm + 22528;
    float* ssg    = sm + 22656;
    float* salpha = sm + 22784;
    float* sred   = sm + 22816;

    const int b = blockIdx.x;
    const int d = threadIdx.x;
    const int warp = d >> 5, lane = d & 31;

    #pragma unroll 4
    for (int l = 0; l < LL; l++) {
        int idx = items[b * LL + l];
        H[l * DD + d] = emb[idx * DD + d];
    }
    for (int i = d; i < LL * LL; i += DD) {
        sAin[i]  = A_in[b * LL * LL + i];
        sAout[i] = A_out[b * LL * LL + i];
    }
    __syncthreads();

    // ---- t_in -> T1, t_out -> T2
    for (int h = 0; h < 2; h++) {
        const int l0 = h * 16;
        ull a0[16], a1[16];
        #pragma unroll
        for (int l = 0; l < 16; l++) { a0[l] = 0ull; a1[l] = 0ull; }
        acc2wp(a0, a1, H, g_Win_p, g_Wout_p, d, l0);
        float bv0 = b_in[d], bv1 = b_out[d];
        #pragma unroll
        for (int l = 0; l < 16; l++) {
            T1[(l0 + l) * DD + d] = psum(a0[l]) + bv0;
            T2[(l0 + l) * DD + d] = psum(a1[l]) + bv1;
        }
    }

    // ---- adjacency (column-private)
    {
        float acc[LL];
        #pragma unroll
        for (int l = 0; l < LL; l++) acc[l] = 0.0f;
        #pragma unroll 4
        for (int m = 0; m < LL; m++) {
            float tv = T1[m * DD + d];
            #pragma unroll
            for (int l = 0; l < LL; l++) acc[l] = fmaf(sAin[l * LL + m], tv, acc[l]);
        }
        #pragma unroll
        for (int l = 0; l < LL; l++) T3[l * DD + d] = acc[l];

        #pragma unroll
        for (int l = 0; l < LL; l++) acc[l] = 0.0f;
        #pragma unroll 4
        for (int m = 0; m < LL; m++) {
            float tv = T2[m * DD + d];
            #pragma unroll
            for (int l = 0; l < LL; l++) acc[l] = fmaf(sAout[l * LL + m], tv, acc[l]);
        }
        #pragma unroll
        for (int l = 0; l < LL; l++) T4[l * DD + d] = acc[l];
    }
    __syncthreads();

    // ================= GGNN GRU =============================================
    for (int h = 0; h < 2; h++) {
        const int l0 = h * 16;
        ull ar[16], az[16], an[16];
        #pragma unroll
        for (int l = 0; l < 16; l++) { ar[l] = az[l] = an[l] = 0ull; }
        acc3p(ar, az, an, T3, g_Wa_p, d, l0);            // a_in rows 0..127
        acc3p(ar, az, an, T4, g_Wa_p + 32 * 384, d, l0); // a_out rows 128..255
        float inv[16];
        {
            float br = b_gru[d], bz = b_gru[DD + d], bn = b_gru[2 * DD + d];
            #pragma unroll
            for (int l = 0; l < 16; l++) {
                T1[(l0 + l) * DD + d] = psum(ar[l]) + br;
                T2[(l0 + l) * DD + d] = psum(az[l]) + bz;
                inv[l] = psum(an[l]) + bn;
            }
        }
        #pragma unroll
        for (int l = 0; l < 16; l++) { ar[l] = az[l] = an[l] = 0ull; }
        acc3p(ar, az, an, H, g_Uh_p, d, l0);
        #pragma unroll
        for (int l = 0; l < 16; l++) {
            float r = sigmoidf_(T1[(l0 + l) * DD + d] + psum(ar[l]));
            float z = sigmoidf_(T2[(l0 + l) * DD + d] + psum(az[l]));
            float n = tanhf(inv[l] + r * psum(an[l]));
            T1[(l0 + l) * DD + d] = (1.0f - z) * n + z * H[(l0 + l) * DD + d];
        }
    }
    __syncthreads();
    #pragma unroll 4
    for (int l = 0; l < LL; l++) {
        T3[l * DD + d] = T1[l * DD + d];
        H[l * DD + d]  = inter[(b * LL + l) * DD + d];
    }
    __syncthreads();

    // ============ ItemFusing GRUCell ========================================
    for (int h = 0; h < 2; h++) {
        const int l0 = h * 16;
        ull ar[16], az[16], an[16];
        #pragma unroll
        for (int l = 0; l < 16; l++) { ar[l] = az[l] = an[l] = 0ull; }
        acc3p(ar, az, an, T3, g_Wi_p, d, l0);
        float inv[16];
        {
            float br = bi[d], bz = bi[DD + d], bn = bi[2 * DD + d];
            #pragma unroll
            for (int l = 0; l < 16; l++) {
                T1[(l0 + l) * DD + d] = psum(ar[l]) + br;
                T2[(l0 + l) * DD + d] = psum(az[l]) + bz;
                inv[l] = psum(an[l]) + bn;
            }
        }
        #pragma unroll
        for (int l = 0; l < 16; l++) { ar[l] = az[l] = an[l] = 0ull; }
        acc3p(ar, az, an, H, g_Wh_p, d, l0);
        {
            float br = bh[d], bz = bh[DD + d], bn = bh[2 * DD + d];
            #pragma unroll
            for (int l = 0; l < 16; l++) {
                float r = sigmoidf_(T1[(l0 + l) * DD + d] + psum(ar[l]) + br);
                float z = sigmoidf_(T2[(l0 + l) * DD + d] + psum(az[l]) + bz);
                float n = tanhf(inv[l] + r * (psum(an[l]) + bn));
                T4[(l0 + l) * DD + d] = (1.0f - z) * n + z * H[(l0 + l) * DD + d];
            }
        }
    }

    // =========================== attention readout ===========================
    const int slen = seq_len[b];
    sv[d] = T4[(slen - 1) * DD + d];
    __syncthreads();

    float q1 = b1[d];
    #pragma unroll 4
    for (int k = 0; k < DD; k++) q1 = fmaf(sv[k], W1[k * DD + d], q1);

    float acc[LL];
    {
        ull aw[LL];
        #pragma unroll
        for (int l = 0; l < LL; l++) aw[l] = 0ull;
        acc1p(aw, T4, g_W2_p, d);
        float bv = b2[d];
        #pragma unroll
        for (int l = 0; l < LL; l++) acc[l] = psum(aw[l]) + bv;
    }
    {
        float wqd = wq[d];
        #pragma unroll
        for (int l = 0; l < LL; l++) {
            float g = sigmoidf_(q1 + acc[l]) * wqd;
            #pragma unroll
            for (int off = 16; off > 0; off >>= 1)
                g += __shfl_xor_sync(0xffffffffu, g, off);
            if (lane == 0) sred[l * 4 + warp] = g;
        }
        __syncthreads();
        if (d < LL) {
            float a_ = sred[d * 4] + sred[d * 4 + 1] + sred[d * 4 + 2] + sred[d * 4 + 3] + bq[0];
            salpha[d] = (d < slen) ? a_ : 0.0f;
        }
        __syncthreads();
    }
    {
        float sg = 0.0f;
        #pragma unroll
        for (int l = 0; l < LL; l++) sg = fmaf(salpha[l], T4[l * DD + d], sg);
        ssg[d] = sg;
    }
    __syncthreads();
    {
        float hs = b3[d];
        #pragma unroll 4
        for (int k = 0; k < DD; k++) hs = fmaf(sv[k], W3[k * DD + d], hs);
        #pragma unroll 4
        for (int k = 0; k < DD; k++) hs = fmaf(ssg[k], W3[(DD + k) * DD + d], hs);
        g_hs[b * DD + d] = hs;
    }
}

// ---------------------------------------------------------------------------
// Kernel 2: scores = h_s @ emb^T via bf16 mma with in-kernel split conversion.
// CTA tile 128x128, full K=128 resident as [hi(256B) | lo(256B)] per row,
// pitch 528B (528 mod 128 = 16 -> conflict-free ldmatrix).
// 3 passes: Ahi.Bhi + Ahi.Blo + Alo.Bhi  (equiv K=384 bf16).
// ---------------------------------------------------------------------------
#define GBM 128
#define GBN 128
#define PITCH 528
#define SMEM_GEMM (2 * 128 * PITCH)   // 135168 B

__device__ __forceinline__ void ldm4(unsigned* r, unsigned saddr) {
    asm volatile("ldmatrix.sync.aligned.m8n8.x4.shared.b16 {%0,%1,%2,%3}, [%4];"
                 : "=r"(r[0]), "=r"(r[1]), "=r"(r[2]), "=r"(r[3]) : "r"(saddr));
}
__device__ __forceinline__ void mma16816(float* c, const unsigned* a, const unsigned* b) {
    asm volatile("mma.sync.aligned.m16n8k16.row.col.f32.bf16.bf16.f32 "
                 "{%0,%1,%2,%3}, {%4,%5,%6,%7}, {%8,%9}, {%0,%1,%2,%3};"
                 : "+f"(c[0]), "+f"(c[1]), "+f"(c[2]), "+f"(c[3])
                 : "r"(a[0]), "r"(a[1]), "r"(a[2]), "r"(a[3]),
                   "r"(b[0]), "r"(b[1]));
}
__device__ __forceinline__ unsigned pkbf2(__nv_bfloat16 a, __nv_bfloat16 b) {
    __nv_bfloat162 t = __halves2bfloat162(a, b);
    return *(unsigned*)&t;
}

// convert float4 -> hi/lo bf16 pairs and store at row base (generic ptr)
__device__ __forceinline__ void store_split(char* rowbase, int c4, float4 v)
{
    __nv_bfloat16 h0 = __float2bfloat16(v.x), h1 = __float2bfloat16(v.y);
    __nv_bfloat16 h2 = __float2bfloat16(v.z), h3 = __float2bfloat16(v.w);
    __nv_bfloat16 l0 = __float2bfloat16(v.x - __bfloat162float(h0));
    __nv_bfloat16 l1 = __float2bfloat16(v.y - __bfloat162float(h1));
    __nv_bfloat16 l2 = __float2bfloat16(v.z - __bfloat162float(h2));
    __nv_bfloat16 l3 = __float2bfloat16(v.w - __bfloat162float(h3));
    *(uint2*)(rowbase + c4 * 8)       = make_uint2(pkbf2(h0, h1), pkbf2(h2, h3));
    *(uint2*)(rowbase + 256 + c4 * 8) = make_uint2(pkbf2(l0, l1), pkbf2(l2, l3));
}

__global__ void __launch_bounds__(256) scores_mma_kernel(const float* __restrict__ emb,
                                                         float* __restrict__ out)
{
    extern __shared__ char smraw[];
    char* aSg = smraw;
    char* bSg = smraw + 128 * PITCH;
    const unsigned sbase = (unsigned)__cvta_generic_to_shared(smraw);
    const unsigned aB = sbase, bB = sbase + 128 * PITCH;

    const int tid = threadIdx.x, lane = tid & 31, w = tid >> 5;
    const int wm = w & 3, wn = w >> 2;            // 4 M-warps x 2 N-warps (32x64 tiles)
    const int bm0 = blockIdx.y * GBM;
    const int n0  = blockIdx.x * GBN;

    // load + convert + store split tiles (A: g_hs, B: emb)
    for (int i = tid; i < 128 * 32; i += 256) {
        int r = i >> 5, c4 = i & 31;
        float4 v = *(const float4*)&g_hs[(size_t)(bm0 + r) * DD + c4 * 4];
        store_split(aSg + r * PITCH, c4, v);
    }
    for (int i = tid; i < 128 * 32; i += 256) {
        int r = i >> 5, c4 = i & 31;
        int n = n0 + r;
        float4 v = make_float4(0.f, 0.f, 0.f, 0.f);
        if (n < NNODE) v = *(const float4*)&emb[(size_t)n * DD + c4 * 4];
        store_split(bSg + r * PITCH, c4, v);
    }
    __syncthreads();

    float acc[2][8][4];
    #pragma unroll
    for (int mi = 0; mi < 2; mi++)
        #pragma unroll
        for (int j = 0; j < 8; j++)
            #pragma unroll
            for (int q = 0; q < 4; q++) acc[mi][j][q] = 0.0f;

    const int a_r  = wm * 32 + (lane & 15);
    const int a_cb = ((lane >> 4) & 1) * 16;
    const int b_r  = wn * 64 + ((lane >> 4) & 1) * 8 + (lane & 7);
    const int b_cb = ((lane >> 3) & 1) * 16;

    const int passA[3] = {0, 0, 256};   // byte offset into row: hi=0, lo=256
    const int passB[3] = {0, 256, 0};

    #pragma unroll
    for (int p = 0; p < 3; p++) {
        const int koA = passA[p], koB = passB[p];
        #pragma unroll
        for (int kk = 0; kk < 8; kk++) {
            unsigned bfr[4][4];
            #pragma unroll
            for (int ni = 0; ni < 4; ni++)
                ldm4(bfr[ni], bB + (b_r + ni * 16) * PITCH + koB + kk * 32 + b_cb);
            #pragma unroll
            for (int mi = 0; mi < 2; mi++) {
                unsigned af[4];
                ldm4(af, aB + (a_r + mi * 16) * PITCH + koA + kk * 32 + a_cb);
                #pragma unroll
                for (int ni = 0; ni < 4; ni++) {
                    mma16816(acc[mi][2 * ni],     af, &bfr[ni][0]);
                    mma16816(acc[mi][2 * ni + 1], af, &bfr[ni][2]);
                }
            }
        }
    }

    // epilogue
    const int r0 = bm0 + wm * 32 + (lane >> 2);
    const int c0 = n0 + wn * 64 + (lane & 3) * 2;
    #pragma unroll
    for (int mi = 0; mi < 2; mi++) {
        int row = r0 + mi * 16;
        #pragma unroll
        for (int j = 0; j < 8; j++) {
            int n = c0 + j * 8;
            if (n < NNODE) {
                *(float2*)&out[(size_t)row * NNODE + n] =
                    make_float2(acc[mi][j][0], acc[mi][j][1]);
                *(float2*)&out[(size_t)(row + 8) * NNODE + n] =
                    make_float2(acc[mi][j][2], acc[mi][j][3]);
            }
        }
    }
}

// ---------------------------------------------------------------------------
extern "C" void kernel_launch(void* const* d_in, const int* in_sizes, int n_in,
                              void* d_out, int out_size)
{
    (void)in_sizes; (void)n_in; (void)out_size;
    const int*   items   = (const int*)d_in[0];
    const float* A_in    = (const float*)d_in[1];
    const float* A_out   = (const float*)d_in[2];
    const float* inter   = (const float*)d_in[3];
    const int*   seq_len = (const int*)d_in[4];
    const float* emb     = (const float*)d_in[5];
    const float* W_in    = (const float*)d_in[6];
    const float* b_in    = (const float*)d_in[7];
    const float* W_out   = (const float*)d_in[8];
    const float* b_out   = (const float*)d_in[9];
    const float* W_a     = (const float*)d_in[10];
    const float* U_h     = (const float*)d_in[11];
    const float* b_gru   = (const float*)d_in[12];
    const float* Wi      = (const float*)d_in[13];
    const float* bi      = (const float*)d_in[14];
    const float* Wh      = (const float*)d_in[15];
    const float* bh      = (const float*)d_in[16];
    const float* W1      = (const float*)d_in[17];
    const float* b1      = (const float*)d_in[18];
    const float* W2      = (const float*)d_in[19];
    const float* b2      = (const float*)d_in[20];
    const float* wq      = (const float*)d_in[21];
    const float* bq      = (const float*)d_in[22];
    const float* W3      = (const float*)d_in[23];
    const float* b3      = (const float*)d_in[24];
    float* out = (float*)d_out;

    const int smem_session = 22944 * 4;          // 91,776 B
    cudaFuncSetAttribute(session_kernel, cudaFuncAttributeMaxDynamicSharedMemorySize,
                         smem_session);
    cudaFuncSetAttribute(scores_mma_kernel, cudaFuncAttributeMaxDynamicSharedMemorySize,
                         SMEM_GEMM);

    pack_weights_kernel<<<288, 256>>>(W_a, U_h, Wi, Wh, W_in, W_out, W2);

    session_kernel<<<BB, 128, smem_session>>>(
        items, A_in, A_out, inter, seq_len, emb,
        b_in, b_out, b_gru, bi, bh,
        W1, b1, b2, wq, bq, W3, b3);

    dim3 grid((NNODE + GBN - 1) / GBN, BB / GBM);   // 391 x 8
    scores_mma_kernel<<<grid, 256, SMEM_GEMM>>>(emb, out);
}

// round 8
// speedup vs baseline: 1.5478x; 1.1526x over previous
#include <cuda_runtime.h>
#include <cuda_bf16.h>
#include <math.h>

#define BB 1024
#define LL 32
#define DD 128
#define NNODE 50000
#define NNODE_PAD 50176   // 196 * 256

typedef unsigned long long ull;

// split-bf16 scratch (K=384 layouts)
// emb:  [hi | lo | hi]   hs: [hi | hi | lo]   =>  A'.B'^T = hi.hi + hi.lo + lo.hi
__device__ __align__(16) __nv_bfloat16 g_embsplit[(size_t)NNODE_PAD * 384];
__device__ __align__(16) __nv_bfloat16 g_hssplit[BB * 384];

// k4-packed weights
__device__ __align__(16) float4 g_Wa_p[64 * 384];
__device__ __align__(16) float4 g_Uh_p[32 * 384];
__device__ __align__(16) float4 g_Wi_p[32 * 384];
__device__ __align__(16) float4 g_Wh_p[32 * 384];
__device__ __align__(16) float4 g_Win_p[32 * 128];
__device__ __align__(16) float4 g_Wout_p[32 * 128];
__device__ __align__(16) float4 g_W2_p[32 * 128];

__device__ __forceinline__ float sigmoidf_(float x) { return 1.0f / (1.0f + expf(-x)); }

__device__ __forceinline__ void fma2(ull& d, ull a, ull b) {
    asm("fma.rn.f32x2 %0, %1, %2, %0;" : "+l"(d) : "l"(a), "l"(b));
}
__device__ __forceinline__ float psum(ull a) {
    float lo, hi; asm("mov.b64 {%0, %1}, %2;" : "=f"(lo), "=f"(hi) : "l"(a));
    return lo + hi;
}
__device__ __forceinline__ unsigned pkbf2(__nv_bfloat16 a, __nv_bfloat16 b) {
    __nv_bfloat162 t = __halves2bfloat162(a, b);
    return *(unsigned*)&t;
}

// ---------------------------------------------------------------------------
// Weight pack kernel
// ---------------------------------------------------------------------------
__device__ __forceinline__ void pack_one(float4* dst, const float* src, int cols, int i)
{
    int k4 = i / cols, c = i - k4 * cols;
    const float* s = src + (size_t)(k4 * 4) * cols + c;
    dst[i] = make_float4(s[0], s[cols], s[2 * cols], s[3 * cols]);
}

__global__ void __launch_bounds__(256) pack_weights_kernel(
    const float* __restrict__ W_a, const float* __restrict__ U_h,
    const float* __restrict__ Wi, const float* __restrict__ Wh,
    const float* __restrict__ W_in, const float* __restrict__ W_out,
    const float* __restrict__ W2)
{
    int idx = blockIdx.x * 256 + threadIdx.x;
    if (idx < 24576)      pack_one(g_Wa_p,  W_a,  384, idx);
    else if (idx < 36864) pack_one(g_Uh_p,  U_h,  384, idx - 24576);
    else if (idx < 49152) pack_one(g_Wi_p,  Wi,   384, idx - 36864);
    else if (idx < 61440) pack_one(g_Wh_p,  Wh,   384, idx - 49152);
    else if (idx < 65536) pack_one(g_Win_p, W_in, 128, idx - 61440);
    else if (idx < 69632) pack_one(g_Wout_p,W_out,128, idx - 65536);
    else if (idx < 73728) pack_one(g_W2_p,  W2,   128, idx - 69632);
}

// ---------------------------------------------------------------------------
// emb -> split bf16 [hi | lo | hi], coalesced 8B stores, zero-pad tail rows
// ---------------------------------------------------------------------------
__global__ void __launch_bounds__(256) split_emb_kernel(const float* __restrict__ emb)
{
    int i = blockIdx.x * 256 + threadIdx.x;          // over NNODE_PAD * 32
    int n = i >> 5, c4 = i & 31;
    float4 v = make_float4(0.f, 0.f, 0.f, 0.f);
    if (n < NNODE) v = *(const float4*)&emb[(size_t)n * DD + c4 * 4];
    __nv_bfloat16 h0 = __float2bfloat16(v.x), h1 = __float2bfloat16(v.y);
    __nv_bfloat16 h2 = __float2bfloat16(v.z), h3 = __float2bfloat16(v.w);
    __nv_bfloat16 l0 = __float2bfloat16(v.x - __bfloat162float(h0));
    __nv_bfloat16 l1 = __float2bfloat16(v.y - __bfloat162float(h1));
    __nv_bfloat16 l2 = __float2bfloat16(v.z - __bfloat162float(h2));
    __nv_bfloat16 l3 = __float2bfloat16(v.w - __bfloat162float(h3));
    char* row = (char*)(g_embsplit + (size_t)n * 384);
    uint2 hi = make_uint2(pkbf2(h0, h1), pkbf2(h2, h3));
    uint2 lo = make_uint2(pkbf2(l0, l1), pkbf2(l2, l3));
    *(uint2*)(row + c4 * 8)       = hi;
    *(uint2*)(row + 256 + c4 * 8) = lo;
    *(uint2*)(row + 512 + c4 * 8) = hi;
}

// ---------------------------------------------------------------------------
// packed accumulate helpers (f32x2)
// ---------------------------------------------------------------------------
__device__ __forceinline__ void acc3p(ull* ar, ull* az, ull* an,
                                      const float* S, const float4* __restrict__ Wp,
                                      int d, int l0)
{
    const ulonglong2* W = (const ulonglong2*)Wp;
    #pragma unroll 2
    for (int k4 = 0; k4 < 32; k4++) {
        const ulonglong2* wb = W + k4 * 384;
        ulonglong2 w0 = wb[d], w1 = wb[128 + d], w2 = wb[256 + d];
        #pragma unroll
        for (int l = 0; l < 16; l++) {
            ulonglong2 s = *(const ulonglong2*)&S[(l0 + l) * DD + k4 * 4];
            fma2(ar[l], s.x, w0.x); fma2(ar[l], s.y, w0.y);
            fma2(az[l], s.x, w1.x); fma2(az[l], s.y, w1.y);
            fma2(an[l], s.x, w2.x); fma2(an[l], s.y, w2.y);
        }
    }
}

__device__ __forceinline__ void acc2wp(ull* a0, ull* a1, const float* S,
                                       const float4* __restrict__ W0p,
                                       const float4* __restrict__ W1p, int d, int l0)
{
    const ulonglong2* W0 = (const ulonglong2*)W0p;
    const ulonglong2* W1 = (const ulonglong2*)W1p;
    #pragma unroll 2
    for (int k4 = 0; k4 < 32; k4++) {
        ulonglong2 w0 = W0[k4 * 128 + d];
        ulonglong2 w1 = W1[k4 * 128 + d];
        #pragma unroll
        for (int l = 0; l < 16; l++) {
            ulonglong2 s = *(const ulonglong2*)&S[(l0 + l) * DD + k4 * 4];
            fma2(a0[l], s.x, w0.x); fma2(a0[l], s.y, w0.y);
            fma2(a1[l], s.x, w1.x); fma2(a1[l], s.y, w1.y);
        }
    }
}

__device__ __forceinline__ void acc1p(ull* a0, const float* S,
                                      const float4* __restrict__ Wp, int d)
{
    const ulonglong2* W = (const ulonglong2*)Wp;
    #pragma unroll 2
    for (int k4 = 0; k4 < 32; k4++) {
        ulonglong2 w = W[k4 * 128 + d];
        #pragma unroll
        for (int l = 0; l < LL; l++) {
            ulonglong2 s = *(const ulonglong2*)&S[l * DD + k4 * 4];
            fma2(a0[l], s.x, w.x); fma2(a0[l], s.y, w.y);
        }
    }
}

// ---------------------------------------------------------------------------
// Kernel 1: session -> g_hssplit
// ---------------------------------------------------------------------------
__global__ void __launch_bounds__(128) session_kernel(
    const int* __restrict__ items, const float* __restrict__ A_in,
    const float* __restrict__ A_out, const float* __restrict__ inter,
    const int* __restrict__ seq_len, const float* __restrict__ emb,
    const float* __restrict__ b_in, const float* __restrict__ b_out,
    const float* __restrict__ b_gru,
    const float* __restrict__ bi, const float* __restrict__ bh,
    const float* __restrict__ W1, const float* __restrict__ b1,
    const float* __restrict__ b2,
    const float* __restrict__ wq, const float* __restrict__ bq,
    const float* __restrict__ W3, const float* __restrict__ b3)
{
    extern __shared__ float sm[];
    float* H      = sm;
    float* T1     = sm + 4096;
    float* T2     = sm + 8192;
    float* T3     = sm + 12288;
    float* T4     = sm + 16384;
    float* sAin   = sm + 20480;
    float* sAout  = sm + 21504;
    float* sv     = sm + 22528;
    float* ssg    = sm + 22656;
    float* salpha = sm + 22784;
    float* sred   = sm + 22816;

    const int b = blockIdx.x;
    const int d = threadIdx.x;
    const int warp = d >> 5, lane = d & 31;

    #pragma unroll 4
    for (int l = 0; l < LL; l++) {
        int idx = items[b * LL + l];
        H[l * DD + d] = emb[idx * DD + d];
    }
    for (int i = d; i < LL * LL; i += DD) {
        sAin[i]  = A_in[b * LL * LL + i];
        sAout[i] = A_out[b * LL * LL + i];
    }
    __syncthreads();

    for (int h = 0; h < 2; h++) {
        const int l0 = h * 16;
        ull a0[16], a1[16];
        #pragma unroll
        for (int l = 0; l < 16; l++) { a0[l] = 0ull; a1[l] = 0ull; }
        acc2wp(a0, a1, H, g_Win_p, g_Wout_p, d, l0);
        float bv0 = b_in[d], bv1 = b_out[d];
        #pragma unroll
        for (int l = 0; l < 16; l++) {
            T1[(l0 + l) * DD + d] = psum(a0[l]) + bv0;
            T2[(l0 + l) * DD + d] = psum(a1[l]) + bv1;
        }
    }

    {
        float acc[LL];
        #pragma unroll
        for (int l = 0; l < LL; l++) acc[l] = 0.0f;
        #pragma unroll 4
        for (int m = 0; m < LL; m++) {
            float tv = T1[m * DD + d];
            #pragma unroll
            for (int l = 0; l < LL; l++) acc[l] = fmaf(sAin[l * LL + m], tv, acc[l]);
        }
        #pragma unroll
        for (int l = 0; l < LL; l++) T3[l * DD + d] = acc[l];

        #pragma unroll
        for (int l = 0; l < LL; l++) acc[l] = 0.0f;
        #pragma unroll 4
        for (int m = 0; m < LL; m++) {
            float tv = T2[m * DD + d];
            #pragma unroll
            for (int l = 0; l < LL; l++) acc[l] = fmaf(sAout[l * LL + m], tv, acc[l]);
        }
        #pragma unroll
        for (int l = 0; l < LL; l++) T4[l * DD + d] = acc[l];
    }
    __syncthreads();

    for (int h = 0; h < 2; h++) {
        const int l0 = h * 16;
        ull ar[16], az[16], an[16];
        #pragma unroll
        for (int l = 0; l < 16; l++) { ar[l] = az[l] = an[l] = 0ull; }
        acc3p(ar, az, an, T3, g_Wa_p, d, l0);
        acc3p(ar, az, an, T4, g_Wa_p + 32 * 384, d, l0);
        float inv[16];
        {
            float br = b_gru[d], bz = b_gru[DD + d], bn = b_gru[2 * DD + d];
            #pragma unroll
            for (int l = 0; l < 16; l++) {
                T1[(l0 + l) * DD + d] = psum(ar[l]) + br;
                T2[(l0 + l) * DD + d] = psum(az[l]) + bz;
                inv[l] = psum(an[l]) + bn;
            }
        }
        #pragma unroll
        for (int l = 0; l < 16; l++) { ar[l] = az[l] = an[l] = 0ull; }
        acc3p(ar, az, an, H, g_Uh_p, d, l0);
        #pragma unroll
        for (int l = 0; l < 16; l++) {
            float r = sigmoidf_(T1[(l0 + l) * DD + d] + psum(ar[l]));
            float z = sigmoidf_(T2[(l0 + l) * DD + d] + psum(az[l]));
            float n = tanhf(inv[l] + r * psum(an[l]));
            T1[(l0 + l) * DD + d] = (1.0f - z) * n + z * H[(l0 + l) * DD + d];
        }
    }
    __syncthreads();
    #pragma unroll 4
    for (int l = 0; l < LL; l++) {
        T3[l * DD + d] = T1[l * DD + d];
        H[l * DD + d]  = inter[(b * LL + l) * DD + d];
    }
    __syncthreads();

    for (int h = 0; h < 2; h++) {
        const int l0 = h * 16;
        ull ar[16], az[16], an[16];
        #pragma unroll
        for (int l = 0; l < 16; l++) { ar[l] = az[l] = an[l] = 0ull; }
        acc3p(ar, az, an, T3, g_Wi_p, d, l0);
        float inv[16];
        {
            float br = bi[d], bz = bi[DD + d], bn = bi[2 * DD + d];
            #pragma unroll
            for (int l = 0; l < 16; l++) {
                T1[(l0 + l) * DD + d] = psum(ar[l]) + br;
                T2[(l0 + l) * DD + d] = psum(az[l]) + bz;
                inv[l] = psum(an[l]) + bn;
            }
        }
        #pragma unroll
        for (int l = 0; l < 16; l++) { ar[l] = az[l] = an[l] = 0ull; }
        acc3p(ar, az, an, H, g_Wh_p, d, l0);
        {
            float br = bh[d], bz = bh[DD + d], bn = bh[2 * DD + d];
            #pragma unroll
            for (int l = 0; l < 16; l++) {
                float r = sigmoidf_(T1[(l0 + l) * DD + d] + psum(ar[l]) + br);
                float z = sigmoidf_(T2[(l0 + l) * DD + d] + psum(az[l]) + bz);
                float n = tanhf(inv[l] + r * (psum(an[l]) + bn));
                T4[(l0 + l) * DD + d] = (1.0f - z) * n + z * H[(l0 + l) * DD + d];
            }
        }
    }

    const int slen = seq_len[b];
    sv[d] = T4[(slen - 1) * DD + d];
    __syncthreads();

    float q1 = b1[d];
    #pragma unroll 4
    for (int k = 0; k < DD; k++) q1 = fmaf(sv[k], W1[k * DD + d], q1);

    float acc[LL];
    {
        ull aw[LL];
        #pragma unroll
        for (int l = 0; l < LL; l++) aw[l] = 0ull;
        acc1p(aw, T4, g_W2_p, d);
        float bv = b2[d];
        #pragma unroll
        for (int l = 0; l < LL; l++) acc[l] = psum(aw[l]) + bv;
    }
    {
        float wqd = wq[d];
        #pragma unroll
        for (int l = 0; l < LL; l++) {
            float g = sigmoidf_(q1 + acc[l]) * wqd;
            #pragma unroll
            for (int off = 16; off > 0; off >>= 1)
                g += __shfl_xor_sync(0xffffffffu, g, off);
            if (lane == 0) sred[l * 4 + warp] = g;
        }
        __syncthreads();
        if (d < LL) {
            float a_ = sred[d * 4] + sred[d * 4 + 1] + sred[d * 4 + 2] + sred[d * 4 + 3] + bq[0];
            salpha[d] = (d < slen) ? a_ : 0.0f;
        }
        __syncthreads();
    }
    {
        float sg = 0.0f;
        #pragma unroll
        for (int l = 0; l < LL; l++) sg = fmaf(salpha[l], T4[l * DD + d], sg);
        ssg[d] = sg;
    }
    __syncthreads();
    {
        float hs = b3[d];
        #pragma unroll 4
        for (int k = 0; k < DD; k++) hs = fmaf(sv[k], W3[k * DD + d], hs);
        #pragma unroll 4
        for (int k = 0; k < DD; k++) hs = fmaf(ssg[k], W3[(DD + k) * DD + d], hs);
        // split write: A' layout [hi | hi | lo]
        __nv_bfloat16 hi = __float2bfloat16(hs);
        __nv_bfloat16 lo = __float2bfloat16(hs - __bfloat162float(hi));
        __nv_bfloat16* row = g_hssplit + (size_t)b * 384;
        row[d] = hi; row[128 + d] = hi; row[256 + d] = lo;
    }
}

// ---------------------------------------------------------------------------
// Kernel 2: scores = hs' @ emb'^T  (K=384 bf16).  512 threads, tile 128x256,
// 16 warps of 32x64, cp.async double-buffered KC=64.  144B smem rows.
// ---------------------------------------------------------------------------
#define GK 384
#define KC 64
#define GBM 128
#define GBN 256
#define ABUF_B (GBM * 144)          // 18432 B
#define BBUF_B (GBN * 144)          // 36864 B
#define STAGE_B (ABUF_B + BBUF_B)   // 55296 B

__device__ __forceinline__ void cp16(unsigned saddr, const void* gptr) {
    asm volatile("cp.async.cg.shared.global [%0], [%1], 16;\n" :: "r"(saddr), "l"(gptr));
}
__device__ __forceinline__ void cp_commit() { asm volatile("cp.async.commit_group;\n"); }
template<int N> __device__ __forceinline__ void cp_wait() {
    asm volatile("cp.async.wait_group %0;\n" :: "n"(N));
}
__device__ __forceinline__ void ldm4(unsigned* r, unsigned saddr) {
    asm volatile("ldmatrix.sync.aligned.m8n8.x4.shared.b16 {%0,%1,%2,%3}, [%4];"
                 : "=r"(r[0]), "=r"(r[1]), "=r"(r[2]), "=r"(r[3]) : "r"(saddr));
}
__device__ __forceinline__ void mma16816(float* c, const unsigned* a, const unsigned* b) {
    asm volatile("mma.sync.aligned.m16n8k16.row.col.f32.bf16.bf16.f32 "
                 "{%0,%1,%2,%3}, {%4,%5,%6,%7}, {%8,%9}, {%0,%1,%2,%3};"
                 : "+f"(c[0]), "+f"(c[1]), "+f"(c[2]), "+f"(c[3])
                 : "r"(a[0]), "r"(a[1]), "r"(a[2]), "r"(a[3]),
                   "r"(b[0]), "r"(b[1]));
}

__global__ void __launch_bounds__(512, 1) scores_mma_kernel(float* __restrict__ out)
{
    extern __shared__ char smraw[];
    const unsigned sbase = (unsigned)__cvta_generic_to_shared(smraw);

    const int tid = threadIdx.x, lane = tid & 31, w = tid >> 5;
    const int wm = w & 3, wn = w >> 2;            // 4 M-warps x 4 N-warps (32x64)
    const int bm0 = blockIdx.y * GBM;
    const int n0  = blockIdx.x * GBN;

    const __nv_bfloat16* Ag0 = g_hssplit + (size_t)bm0 * GK;
    const __nv_bfloat16* Bg0 = g_embsplit + (size_t)n0 * GK;

    const int lr = tid >> 3, lc8 = tid & 7;       // lr 0..63

    auto load_stage = [&](int s, int buf) {
        unsigned ab = sbase + buf * STAGE_B;
        unsigned bb = ab + ABUF_B;
        const __nv_bfloat16* Ag = Ag0 + s * KC;
        const __nv_bfloat16* Bg = Bg0 + s * KC;
        #pragma unroll
        for (int i = 0; i < 2; i++) {             // A: 128 rows
            int r = lr + i * 64;
            cp16(ab + r * 144 + lc8 * 16, Ag + (size_t)r * GK + lc8 * 8);
        }
        #pragma unroll
        for (int i = 0; i < 4; i++) {             // B: 256 rows
            int r = lr + i * 64;
            cp16(bb + r * 144 + lc8 * 16, Bg + (size_t)r * GK + lc8 * 8);
        }
    };

    float acc[2][8][4];
    #pragma unroll
    for (int mi = 0; mi < 2; mi++)
        #pragma unroll
        for (int j = 0; j < 8; j++)
            #pragma unroll
            for (int q = 0; q < 4; q++) acc[mi][j][q] = 0.0f;

    const int a_r  = wm * 32 + (lane & 15);
    const int a_cb = ((lane >> 4) & 1) * 16;
    const int b_r  = wn * 64 + ((lane >> 4) & 1) * 8 + (lane & 7);
    const int b_cb = ((lane >> 3) & 1) * 16;

    load_stage(0, 0);
    cp_commit();

    #pragma unroll
    for (int s = 0; s < GK / KC; s++) {
        if (s < GK / KC - 1) {
            load_stage(s + 1, (s + 1) & 1);
            cp_commit();
            cp_wait<1>();
        } else {
            cp_wait<0>();
        }
        __syncthreads();

        unsigned ab = sbase + (s & 1) * STAGE_B;
        unsigned bb = ab + ABUF_B;

        #pragma unroll
        for (int kk = 0; kk < KC / 16; kk++) {
            unsigned bfr[4][4];
            #pragma unroll
            for (int ni = 0; ni < 4; ni++)
                ldm4(bfr[ni], bb + (b_r + ni * 16) * 144 + kk * 32 + b_cb);
            #pragma unroll
            for (int mi = 0; mi < 2; mi++) {
                unsigned af[4];
                ldm4(af, ab + (a_r + mi * 16) * 144 + kk * 32 + a_cb);
                #pragma unroll
                for (int ni = 0; ni < 4; ni++) {
                    mma16816(acc[mi][2 * ni],     af, &bfr[ni][0]);
                    mma16816(acc[mi][2 * ni + 1], af, &bfr[ni][2]);
                }
            }
        }
        __syncthreads();
    }

    const int r0 = bm0 + wm * 32 + (lane >> 2);
    const int c0 = n0 + wn * 64 + (lane & 3) * 2;
    #pragma unroll
    for (int mi = 0; mi < 2; mi++) {
        int row = r0 + mi * 16;
        #pragma unroll
        for (int j = 0; j < 8; j++) {
            int n = c0 + j * 8;
            if (n < NNODE) {
                *(float2*)&out[(size_t)row * NNODE + n] =
                    make_float2(acc[mi][j][0], acc[mi][j][1]);
                *(float2*)&out[(size_t)(row + 8) * NNODE + n] =
                    make_float2(acc[mi][j][2], acc[mi][j][3]);
            }
        }
    }
}

// ---------------------------------------------------------------------------
extern "C" void kernel_launch(void* const* d_in, const int* in_sizes, int n_in,
                              void* d_out, int out_size)
{
    (void)in_sizes; (void)n_in; (void)out_size;
    const int*   items   = (const int*)d_in[0];
    const float* A_in    = (const float*)d_in[1];
    const float* A_out   = (const float*)d_in[2];
    const float* inter   = (const float*)d_in[3];
    const int*   seq_len = (const int*)d_in[4];
    const float* emb     = (const float*)d_in[5];
    const float* W_in    = (const float*)d_in[6];
    const float* b_in    = (const float*)d_in[7];
    const float* W_out   = (const float*)d_in[8];
    const float* b_out   = (const float*)d_in[9];
    const float* W_a     = (const float*)d_in[10];
    const float* U_h     = (const float*)d_in[11];
    const float* b_gru   = (const float*)d_in[12];
    const float* Wi      = (const float*)d_in[13];
    const float* bi      = (const float*)d_in[14];
    const float* Wh      = (const float*)d_in[15];
    const float* bh      = (const float*)d_in[16];
    const float* W1      = (const float*)d_in[17];
    const float* b1      = (const float*)d_in[18];
    const float* W2      = (const float*)d_in[19];
    const float* b2      = (const float*)d_in[20];
    const float* wq      = (const float*)d_in[21];
    const float* bq      = (const float*)d_in[22];
    const float* W3      = (const float*)d_in[23];
    const float* b3      = (const float*)d_in[24];
    float* out = (float*)d_out;

    const int smem_session = 22944 * 4;          // 91,776 B
    const int smem_gemm    = 2 * STAGE_B;        // 110,592 B
    cudaFuncSetAttribute(session_kernel, cudaFuncAttributeMaxDynamicSharedMemorySize,
                         smem_session);
    cudaFuncSetAttribute(scores_mma_kernel, cudaFuncAttributeMaxDynamicSharedMemorySize,
                         smem_gemm);

    pack_weights_kernel<<<288, 256>>>(W_a, U_h, Wi, Wh, W_in, W_out, W2);
    split_emb_kernel<<<(NNODE_PAD * 32) / 256, 256>>>(emb);

    session_kernel<<<BB, 128, smem_session>>>(
        items, A_in, A_out, inter, seq_len, emb,
        b_in, b_out, b_gru, bi, bh,
        W1, b1, b2, wq, bq, W3, b3);

    dim3 grid(NNODE_PAD / GBN, BB / GBM);        // 196 x 8
    scores_mma_kernel<<<grid, 512, smem_gemm>>>(out);
}

// round 10
// speedup vs baseline: 1.9254x; 1.2440x over previous
#include <cuda_runtime.h>
#include <cuda_bf16.h>
#include <math.h>

#define BB 1024
#define LL 32
#define DD 128
#define NNODE 50000
#define NNODE_PAD 50176   // 196 * 256
#define MROWS (BB * LL)   // 32768

typedef unsigned long long ull;

// ---------------- global scratch ----------------
// split-bf16 operands ([hi | lo] along K)
__device__ __align__(16) __nv_bfloat16 g_embsplit[(size_t)NNODE_PAD * 384]; // [hi|lo|hi]
__device__ __align__(16) __nv_bfloat16 g_hssplit[BB * 384];                 // [hi|hi|lo]
__device__ __align__(16) __nv_bfloat16 g_A1s[(size_t)MROWS * 512];  // [a_in|a_out] K=256 split
__device__ __align__(16) __nv_bfloat16 g_Hs[(size_t)MROWS * 256];   // h K=128 split
__device__ __align__(16) __nv_bfloat16 g_inters[(size_t)MROWS * 256];
__device__ __align__(16) __nv_bfloat16 g_intras[(size_t)MROWS * 256];
__device__ float g_H[(size_t)MROWS * 128];      // h fp32
__device__ float g_P[(size_t)MROWS * 384];      // GEMM outputs (reused)
__device__ float g_Q[(size_t)MROWS * 384];
__device__ float g_final[(size_t)MROWS * 128];

// weights: split-bf16 TRANSPOSED  Bw[n, k] = split(W[k, n]),  [hi(K)|lo(K)]
__device__ __align__(16) __nv_bfloat16 g_Wat[384 * 512];   // W_a  [256,384] -> [384,512]
__device__ __align__(16) __nv_bfloat16 g_Uht[384 * 256];   // U_h
__device__ __align__(16) __nv_bfloat16 g_Wit[384 * 256];   // Wi
__device__ __align__(16) __nv_bfloat16 g_Wht[384 * 256];   // Wh
// f4-packed fp32 weights for CUDA-core paths
__device__ __align__(16) float4 g_Win_p[32 * 128];
__device__ __align__(16) float4 g_Wout_p[32 * 128];
__device__ __align__(16) float4 g_W2_p[32 * 128];

__device__ __forceinline__ float sigmoidf_(float x) { return 1.0f / (1.0f + expf(-x)); }

__device__ __forceinline__ void fma2(ull& d, ull a, ull b) {
    asm("fma.rn.f32x2 %0, %1, %2, %0;" : "+l"(d) : "l"(a), "l"(b));
}
__device__ __forceinline__ float psum(ull a) {
    float lo, hi; asm("mov.b64 {%0, %1}, %2;" : "=f"(lo), "=f"(hi) : "l"(a));
    return lo + hi;
}
__device__ __forceinline__ unsigned pkbf2(__nv_bfloat16 a, __nv_bfloat16 b) {
    __nv_bfloat162 t = __halves2bfloat162(a, b);
    return *(unsigned*)&t;
}
__device__ __forceinline__ void split_w(float w, __nv_bfloat16& hi, __nv_bfloat16& lo) {
    hi = __float2bfloat16(w);
    lo = __float2bfloat16(w - __bfloat162float(hi));
}

// ---------------------------------------------------------------------------
// Weight pack kernel
// ---------------------------------------------------------------------------
__device__ __forceinline__ void pack_one(float4* dst, const float* src, int cols, int i)
{
    int k4 = i / cols, c = i - k4 * cols;
    const float* s = src + (size_t)(k4 * 4) * cols + c;
    dst[i] = make_float4(s[0], s[cols], s[2 * cols], s[3 * cols]);
}
__device__ __forceinline__ void pack_wt(__nv_bfloat16* dst, const float* src,
                                        int K, int i)
{   // i over 384*K ; n = i/K, k = i%K ; dst [384, 2K]
    int n = i / K, k = i - n * K;
    __nv_bfloat16 hi, lo; split_w(src[(size_t)k * 384 + n], hi, lo);
    dst[(size_t)n * (2 * K) + k] = hi;
    dst[(size_t)n * (2 * K) + K + k] = lo;
}

__global__ void __launch_bounds__(256) pack_weights_kernel(
    const float* __restrict__ W_a, const float* __restrict__ U_h,
    const float* __restrict__ Wi, const float* __restrict__ Wh,
    const float* __restrict__ W_in, const float* __restrict__ W_out,
    const float* __restrict__ W2)
{
    int idx = blockIdx.x * 256 + threadIdx.x;
    if (idx < 98304)       pack_wt(g_Wat, W_a, 256, idx);
    else if (idx < 147456) pack_wt(g_Uht, U_h, 128, idx - 98304);
    else if (idx < 196608) pack_wt(g_Wit, Wi, 128, idx - 147456);
    else if (idx < 245760) pack_wt(g_Wht, Wh, 128, idx - 196608);
    else if (idx < 249856) pack_one(g_Win_p, W_in, 128, idx - 245760);
    else if (idx < 253952) pack_one(g_Wout_p, W_out, 128, idx - 249856);
    else if (idx < 258048) pack_one(g_W2_p, W2, 128, idx - 253952);
}

// ---------------------------------------------------------------------------
// emb -> split bf16 [hi | lo | hi]
// ---------------------------------------------------------------------------
__global__ void __launch_bounds__(256) split_emb_kernel(const float* __restrict__ emb)
{
    int i = blockIdx.x * 256 + threadIdx.x;          // over NNODE_PAD * 32
    int n = i >> 5, c4 = i & 31;
    float4 v = make_float4(0.f, 0.f, 0.f, 0.f);
    if (n < NNODE) v = *(const float4*)&emb[(size_t)n * DD + c4 * 4];
    __nv_bfloat16 h0, l0, h1, l1, h2, l2, h3, l3;
    split_w(v.x, h0, l0); split_w(v.y, h1, l1);
    split_w(v.z, h2, l2); split_w(v.w, h3, l3);
    char* row = (char*)(g_embsplit + (size_t)n * 384);
    uint2 hi = make_uint2(pkbf2(h0, h1), pkbf2(h2, h3));
    uint2 lo = make_uint2(pkbf2(l0, l1), pkbf2(l2, l3));
    *(uint2*)(row + c4 * 8)       = hi;
    *(uint2*)(row + 256 + c4 * 8) = lo;
    *(uint2*)(row + 512 + c4 * 8) = hi;
}

// ---------------------------------------------------------------------------
// f32x2 helpers for kernel A / readout
// ---------------------------------------------------------------------------
__device__ __forceinline__ void acc2wp(ull* a0, ull* a1, const float* S,
                                       const float4* __restrict__ W0p,
                                       const float4* __restrict__ W1p, int d, int l0)
{
    const ulonglong2* W0 = (const ulonglong2*)W0p;
    const ulonglong2* W1 = (const ulonglong2*)W1p;
    #pragma unroll 2
    for (int k4 = 0; k4 < 32; k4++) {
        ulonglong2 w0 = W0[k4 * 128 + d];
        ulonglong2 w1 = W1[k4 * 128 + d];
        #pragma unroll
        for (int l = 0; l < 16; l++) {
            ulonglong2 s = *(const ulonglong2*)&S[(l0 + l) * DD + k4 * 4];
            fma2(a0[l], s.x, w0.x); fma2(a0[l], s.y, w0.y);
            fma2(a1[l], s.x, w1.x); fma2(a1[l], s.y, w1.y);
        }
    }
}
__device__ __forceinline__ void acc1p(ull* a0, const float* S,
                                      const float4* __restrict__ Wp, int d)
{
    const ulonglong2* W = (const ulonglong2*)Wp;
    #pragma unroll 2
    for (int k4 = 0; k4 < 32; k4++) {
        ulonglong2 w = W[k4 * 128 + d];
        #pragma unroll
        for (int l = 0; l < LL; l++) {
            ulonglong2 s = *(const ulonglong2*)&S[l * DD + k4 * 4];
            fma2(a0[l], s.x, w.x); fma2(a0[l], s.y, w.y);
        }
    }
}

// ---------------------------------------------------------------------------
// Kernel A: embed + Win/Wout + adjacency -> split operands
// ---------------------------------------------------------------------------
__global__ void __launch_bounds__(128) kernelA(
    const int* __restrict__ items, const float* __restrict__ A_in,
    const float* __restrict__ A_out, const float* __restrict__ inter,
    const float* __restrict__ emb,
    const float* __restrict__ b_in, const float* __restrict__ b_out)
{
    extern __shared__ float sm[];
    float* H     = sm;            // 4096
    float* T1    = sm + 4096;
    float* T2    = sm + 8192;
    float* sAin  = sm + 12288;
    float* sAout = sm + 13312;    // total 14336 floats

    const int b = blockIdx.x;
    const int d = threadIdx.x;

    #pragma unroll 4
    for (int l = 0; l < LL; l++) {
        int idx = items[b * LL + l];
        H[l * DD + d] = emb[(size_t)idx * DD + d];
    }
    for (int i = d; i < LL * LL; i += DD) {
        sAin[i]  = A_in[b * LL * LL + i];
        sAout[i] = A_out[b * LL * LL + i];
    }
    __syncthreads();

    // H split + fp32, inter split  (own column writes)
    #pragma unroll 4
    for (int l = 0; l < LL; l++) {
        size_t row = (size_t)b * LL + l;
        float hv = H[l * DD + d];
        g_H[row * 128 + d] = hv;
        __nv_bfloat16 hi, lo; split_w(hv, hi, lo);
        g_Hs[row * 256 + d] = hi; g_Hs[row * 256 + 128 + d] = lo;
        float iv = inter[row * 128 + d];
        split_w(iv, hi, lo);
        g_inters[row * 256 + d] = hi; g_inters[row * 256 + 128 + d] = lo;
    }

    // t_in -> T1, t_out -> T2
    for (int h = 0; h < 2; h++) {
        const int l0 = h * 16;
        ull a0[16], a1[16];
        #pragma unroll
        for (int l = 0; l < 16; l++) { a0[l] = 0ull; a1[l] = 0ull; }
        acc2wp(a0, a1, H, g_Win_p, g_Wout_p, d, l0);
        float bv0 = b_in[d], bv1 = b_out[d];
        #pragma unroll
        for (int l = 0; l < 16; l++) {
            T1[(l0 + l) * DD + d] = psum(a0[l]) + bv0;
            T2[(l0 + l) * DD + d] = psum(a1[l]) + bv1;
        }
    }
    // adjacency: a_in = A_in @ T1, a_out = A_out @ T2  (own column)
    {
        float acc[LL];
        #pragma unroll
        for (int l = 0; l < LL; l++) acc[l] = 0.0f;
        #pragma unroll 4
        for (int m = 0; m < LL; m++) {
            float tv = T1[m * DD + d];
            #pragma unroll
            for (int l = 0; l < LL; l++) acc[l] = fmaf(sAin[l * LL + m], tv, acc[l]);
        }
        #pragma unroll
        for (int l = 0; l < LL; l++) {
            size_t row = (size_t)b * LL + l;
            __nv_bfloat16 hi, lo; split_w(acc[l], hi, lo);
            g_A1s[row * 512 + d] = hi;          // a_in hi at k=d
            g_A1s[row * 512 + 256 + d] = lo;    // a_in lo
        }
        #pragma unroll
        for (int l = 0; l < LL; l++) acc[l] = 0.0f;
        #pragma unroll 4
        for (int m = 0; m < LL; m++) {
            float tv = T2[m * DD + d];
            #pragma unroll
            for (int l = 0; l < LL; l++) acc[l] = fmaf(sAout[l * LL + m], tv, acc[l]);
        }
        #pragma unroll
        for (int l = 0; l < LL; l++) {
            size_t row = (size_t)b * LL + l;
            __nv_bfloat16 hi, lo; split_w(acc[l], hi, lo);
            g_A1s[row * 512 + 128 + d] = hi;    // a_out hi at k=128+d
            g_A1s[row * 512 + 384 + d] = lo;
        }
    }
}

// ---------------------------------------------------------------------------
// Generic split-bf16 GEMM:  C[M,384] = A[M,K] @ W[K,384]
// A stored [M, 2K] = [hi|lo], Bw stored [384, 2K] = [hi|lo] (transposed W)
// 3 passes: hi.hi + hi.lo + lo.hi.  Tile 256x128, 512 thr, KC=64 dbl-buffered.
// ---------------------------------------------------------------------------
#define SG_AB (256 * 144)            // 36864
#define SG_BB (128 * 144)            // 18432
#define SG_STAGE (SG_AB + SG_BB)     // 55296

__device__ __forceinline__ void cp16(unsigned saddr, const void* gptr) {
    asm volatile("cp.async.cg.shared.global [%0], [%1], 16;\n" :: "r"(saddr), "l"(gptr));
}
__device__ __forceinline__ void cp_commit() { asm volatile("cp.async.commit_group;\n"); }
template<int N> __device__ __forceinline__ void cp_wait() {
    asm volatile("cp.async.wait_group %0;\n" :: "n"(N));
}
__device__ __forceinline__ void ldm4(unsigned* r, unsigned saddr) {
    asm volatile("ldmatrix.sync.aligned.m8n8.x4.shared.b16 {%0,%1,%2,%3}, [%4];"
                 : "=r"(r[0]), "=r"(r[1]), "=r"(r[2]), "=r"(r[3]) : "r"(saddr));
}
__device__ __forceinline__ void mma16816(float* c, const unsigned* a, const unsigned* b) {
    asm volatile("mma.sync.aligned.m16n8k16.row.col.f32.bf16.bf16.f32 "
                 "{%0,%1,%2,%3}, {%4,%5,%6,%7}, {%8,%9}, {%0,%1,%2,%3};"
                 : "+f"(c[0]), "+f"(c[1]), "+f"(c[2]), "+f"(c[3])
                 : "r"(a[0]), "r"(a[1]), "r"(a[2]), "r"(a[3]),
                   "r"(b[0]), "r"(b[1]));
}

template<int KK>
__global__ void __launch_bounds__(512, 1) gemm_split_kernel(
    const __nv_bfloat16* __restrict__ A, const __nv_bfloat16* __restrict__ Bw,
    float* __restrict__ C)
{
    extern __shared__ char smraw[];
    const unsigned sbase = (unsigned)__cvta_generic_to_shared(smraw);

    const int tid = threadIdx.x, lane = tid & 31, w = tid >> 5;
    const int wm = w & 7, wn = w >> 3;           // 8 M-warps x 2 N-warps (32x64)
    const int m0 = blockIdx.y * 256;
    const int n0 = blockIdx.x * 128;
    const int lr = tid >> 3, lc8 = tid & 7;      // lr 0..63

    const int NCH = KK / 64;
    const int aoffs[3] = {0, 0, KK};
    const int boffs[3] = {0, KK, 0};

    auto load_stage = [&](int s, int buf) {
        int p = s / NCH, cc = s - p * NCH;
        int ga = aoffs[p] + cc * 64, gb = boffs[p] + cc * 64;
        unsigned ab = sbase + buf * SG_STAGE;
        unsigned bb = ab + SG_AB;
        #pragma unroll
        for (int i = 0; i < 4; i++) {            // A: 256 rows
            int r = lr + i * 64;
            cp16(ab + r * 144 + lc8 * 16,
                 A + (size_t)(m0 + r) * (2 * KK) + ga + lc8 * 8);
        }
        #pragma unroll
        for (int i = 0; i < 2; i++) {            // B: 128 rows
            int r = lr + i * 64;
            cp16(bb + r * 144 + lc8 * 16,
                 Bw + (size_t)(n0 + r) * (2 * KK) + gb + lc8 * 8);
        }
    };

    float acc[2][8][4];
    #pragma unroll
    for (int mi = 0; mi < 2; mi++)
        #pragma unroll
        for (int j = 0; j < 8; j++)
            #pragma unroll
            for (int q = 0; q < 4; q++) acc[mi][j][q] = 0.0f;

    const int a_r  = wm * 32 + (lane & 15);
    const int a_cb = ((lane >> 4) & 1) * 16;
    const int b_r  = wn * 64 + ((lane >> 4) & 1) * 8 + (lane & 7);
    const int b_cb = ((lane >> 3) & 1) * 16;

    const int NS = 3 * NCH;
    load_stage(0, 0);
    cp_commit();

    for (int s = 0; s < NS; s++) {
        if (s < NS - 1) {
            load_stage(s + 1, (s + 1) & 1);
            cp_commit();
            cp_wait<1>();
        } else {
            cp_wait<0>();
        }
        __syncthreads();

        unsigned ab = sbase + (s & 1) * SG_STAGE;
        unsigned bb = ab + SG_AB;

        #pragma unroll
        for (int kk = 0; kk < 4; kk++) {
            unsigned bfr[4][4];
            #pragma unroll
            for (int ni = 0; ni < 4; ni++)
                ldm4(bfr[ni], bb + (b_r + ni * 16) * 144 + kk * 32 + b_cb);
            #pragma unroll
            for (int mi = 0; mi < 2; mi++) {
                unsigned af[4];
                ldm4(af, ab + (a_r + mi * 16) * 144 + kk * 32 + a_cb);
                #pragma unroll
                for (int ni = 0; ni < 4; ni++) {
                    mma16816(acc[mi][2 * ni],     af, &bfr[ni][0]);
                    mma16816(acc[mi][2 * ni + 1], af, &bfr[ni][2]);
                }
            }
        }
        __syncthreads();
    }

    const int r0 = m0 + wm * 32 + (lane >> 2);
    const int c0 = n0 + wn * 64 + (lane & 3) * 2;
    #pragma unroll
    for (int mi = 0; mi < 2; mi++) {
        int row = r0 + mi * 16;
        #pragma unroll
        for (int j = 0; j < 8; j++) {
            int n = c0 + j * 8;
            *(float2*)&C[(size_t)row * 384 + n] =
                make_float2(acc[mi][j][0], acc[mi][j][1]);
            *(float2*)&C[(size_t)(row + 8) * 384 + n] =
                make_float2(acc[mi][j][2], acc[mi][j][3]);
        }
    }
}

// ---------------------------------------------------------------------------
// GRU gate kernels
// ---------------------------------------------------------------------------
__global__ void __launch_bounds__(256) gates1_kernel(const float* __restrict__ b_gru)
{
    int idx = blockIdx.x * 256 + threadIdx.x;   // over MROWS*128
    int row = idx >> 7, d = idx & 127;
    const float* P = g_P + (size_t)row * 384;
    const float* Q = g_Q + (size_t)row * 384;
    float r = sigmoidf_(P[d] + Q[d] + b_gru[d]);
    float z = sigmoidf_(P[128 + d] + Q[128 + d] + b_gru[128 + d]);
    float n = tanhf(P[256 + d] + b_gru[256 + d] + r * Q[256 + d]);
    float h = g_H[idx];
    float intra = (1.0f - z) * n + z * h;
    __nv_bfloat16 hi, lo; split_w(intra, hi, lo);
    g_intras[(size_t)row * 256 + d] = hi;
    g_intras[(size_t)row * 256 + 128 + d] = lo;
}

__global__ void __launch_bounds__(256) gates2_kernel(
    const float* __restrict__ bi, const float* __restrict__ bh,
    const float* __restrict__ inter)
{
    int idx = blockIdx.x * 256 + threadIdx.x;
    int row = idx >> 7, d = idx & 127;
    const float* P = g_P + (size_t)row * 384;   // intra@Wi
    const float* Q = g_Q + (size_t)row * 384;   // inter@Wh
    float r = sigmoidf_(P[d] + bi[d] + Q[d] + bh[d]);
    float z = sigmoidf_(P[128 + d] + bi[128 + d] + Q[128 + d] + bh[128 + d]);
    float n = tanhf(P[256 + d] + bi[256 + d] + r * (Q[256 + d] + bh[256 + d]));
    float iv = inter[idx];
    g_final[idx] = (1.0f - z) * n + z * iv;
}

// ---------------------------------------------------------------------------
// Readout: attention + W3 -> g_hssplit   (per-batch CTA, 128 threads)
// ---------------------------------------------------------------------------
__global__ void __launch_bounds__(128) readout_kernel(
    const int* __restrict__ seq_len,
    const float* __restrict__ W1, const float* __restrict__ b1,
    const float* __restrict__ b2,
    const float* __restrict__ wq, const float* __restrict__ bq,
    const float* __restrict__ W3, const float* __restrict__ b3)
{
    __shared__ float Tf[LL * DD];
    __shared__ float sv[DD], ssg[DD], salpha[LL], sred[DD];

    const int b = blockIdx.x;
    const int d = threadIdx.x;
    const int warp = d >> 5, lane = d & 31;

    #pragma unroll 4
    for (int l = 0; l < LL; l++)
        Tf[l * DD + d] = g_final[((size_t)b * LL + l) * DD + d];

    const int slen = seq_len[b];
    sv[d] = Tf[(slen - 1) * DD + d];   // own column
    __syncthreads();

    float q1 = b1[d];
    #pragma unroll 4
    for (int k = 0; k < DD; k++) q1 = fmaf(sv[k], W1[k * DD + d], q1);

    float acc[LL];
    {
        ull aw[LL];
        #pragma unroll
        for (int l = 0; l < LL; l++) aw[l] = 0ull;
        acc1p(aw, Tf, g_W2_p, d);
        float bv = b2[d];
        #pragma unroll
        for (int l = 0; l < LL; l++) acc[l] = psum(aw[l]) + bv;
    }
    {
        float wqd = wq[d];
        #pragma unroll
        for (int l = 0; l < LL; l++) {
            float g = sigmoidf_(q1 + acc[l]) * wqd;
            #pragma unroll
            for (int off = 16; off > 0; off >>= 1)
                g += __shfl_xor_sync(0xffffffffu, g, off);
            if (lane == 0) sred[l * 4 + warp] = g;
        }
        __syncthreads();
        if (d < LL) {
            float a_ = sred[d * 4] + sred[d * 4 + 1] + sred[d * 4 + 2] + sred[d * 4 + 3] + bq[0];
            salpha[d] = (d < slen) ? a_ : 0.0f;
        }
        __syncthreads();
    }
    {
        float sg = 0.0f;
        #pragma unroll
        for (int l = 0; l < LL; l++) sg = fmaf(salpha[l], Tf[l * DD + d], sg);
        ssg[d] = sg;
    }
    __syncthreads();
    {
        float hs = b3[d];
        #pragma unroll 4
        for (int k = 0; k < DD; k++) hs = fmaf(sv[k], W3[k * DD + d], hs);
        #pragma unroll 4
        for (int k = 0; k < DD; k++) hs = fmaf(ssg[k], W3[(DD + k) * DD + d], hs);
        __nv_bfloat16 hi, lo; split_w(hs, hi, lo);
        __nv_bfloat16* row = g_hssplit + (size_t)b * 384;
        row[d] = hi; row[128 + d] = hi; row[256 + d] = lo;
    }
}

// ---------------------------------------------------------------------------
// Scores GEMM (unchanged from round 8): tile 128x256, K=384, 512 threads
// ---------------------------------------------------------------------------
#define SC_AB (128 * 144)
#define SC_BB (256 * 144)
#define SC_STAGE (SC_AB + SC_BB)

__global__ void __launch_bounds__(512, 1) scores_mma_kernel(float* __restrict__ out)
{
    extern __shared__ char smraw[];
    const unsigned sbase = (unsigned)__cvta_generic_to_shared(smraw);

    const int tid = threadIdx.x, lane = tid & 31, w = tid >> 5;
    const int wm = w & 3, wn = w >> 2;            // 4 M x 4 N (32x64)
    const int bm0 = blockIdx.y * 128;
    const int n0  = blockIdx.x * 256;

    const __nv_bfloat16* Ag0 = g_hssplit + (size_t)bm0 * 384;
    const __nv_bfloat16* Bg0 = g_embsplit + (size_t)n0 * 384;

    const int lr = tid >> 3, lc8 = tid & 7;

    auto load_stage = [&](int s, int buf) {
        unsigned ab = sbase + buf * SC_STAGE;
        unsigned bb = ab + SC_AB;
        const __nv_bfloat16* Ag = Ag0 + s * 64;
        const __nv_bfloat16* Bg = Bg0 + s * 64;
        #pragma unroll
        for (int i = 0; i < 2; i++) {
            int r = lr + i * 64;
            cp16(ab + r * 144 + lc8 * 16, Ag + (size_t)r * 384 + lc8 * 8);
        }
        #pragma unroll
        for (int i = 0; i < 4; i++) {
            int r = lr + i * 64;
            cp16(bb + r * 144 + lc8 * 16, Bg + (size_t)r * 384 + lc8 * 8);
        }
    };

    float acc[2][8][4];
    #pragma unroll
    for (int mi = 0; mi < 2; mi++)
        #pragma unroll
        for (int j = 0; j < 8; j++)
            #pragma unroll
            for (int q = 0; q < 4; q++) acc[mi][j][q] = 0.0f;

    const int a_r  = wm * 32 + (lane & 15);
    const int a_cb = ((lane >> 4) & 1) * 16;
    const int b_r  = wn * 64 + ((lane >> 4) & 1) * 8 + (lane & 7);
    const int b_cb = ((lane >> 3) & 1) * 16;

    load_stage(0, 0);
    cp_commit();

    #pragma unroll
    for (int s = 0; s < 6; s++) {
        if (s < 5) {
            load_stage(s + 1, (s + 1) & 1);
            cp_commit();
            cp_wait<1>();
        } else {
            cp_wait<0>();
        }
        __syncthreads();

        unsigned ab = sbase + (s & 1) * SC_STAGE;
        unsigned bb = ab + SC_AB;

        #pragma unroll
        for (int kk = 0; kk < 4; kk++) {
            unsigned bfr[4][4];
            #pragma unroll
            for (int ni = 0; ni < 4; ni++)
                ldm4(bfr[ni], bb + (b_r + ni * 16) * 144 + kk * 32 + b_cb);
            #pragma unroll
            for (int mi = 0; mi < 2; mi++) {
                unsigned af[4];
                ldm4(af, ab + (a_r + mi * 16) * 144 + kk * 32 + a_cb);
                #pragma unroll
                for (int ni = 0; ni < 4; ni++) {
                    mma16816(acc[mi][2 * ni],     af, &bfr[ni][0]);
                    mma16816(acc[mi][2 * ni + 1], af, &bfr[ni][2]);
                }
            }
        }
        __syncthreads();
    }

    const int r0 = bm0 + wm * 32 + (lane >> 2);
    const int c0 = n0 + wn * 64 + (lane & 3) * 2;
    #pragma unroll
    for (int mi = 0; mi < 2; mi++) {
        int row = r0 + mi * 16;
        #pragma unroll
        for (int j = 0; j < 8; j++) {
            int n = c0 + j * 8;
            if (n < NNODE) {
                *(float2*)&out[(size_t)row * NNODE + n] =
                    make_float2(acc[mi][j][0], acc[mi][j][1]);
                *(float2*)&out[(size_t)(row + 8) * NNODE + n] =
                    make_float2(acc[mi][j][2], acc[mi][j][3]);
            }
        }
    }
}

// ---------------------------------------------------------------------------
extern "C" void kernel_launch(void* const* d_in, const int* in_sizes, int n_in,
                              void* d_out, int out_size)
{
    (void)in_sizes; (void)n_in; (void)out_size;
    const int*   items   = (const int*)d_in[0];
    const float* A_in    = (const float*)d_in[1];
    const float* A_out   = (const float*)d_in[2];
    const float* inter   = (const float*)d_in[3];
    const int*   seq_len = (const int*)d_in[4];
    const float* emb     = (const float*)d_in[5];
    const float* W_in    = (const float*)d_in[6];
    const float* b_in    = (const float*)d_in[7];
    const float* W_out   = (const float*)d_in[8];
    const float* b_out   = (const float*)d_in[9];
    const float* W_a     = (const float*)d_in[10];
    const float* U_h     = (const float*)d_in[11];
    const float* b_gru   = (const float*)d_in[12];
    const float* Wi      = (const float*)d_in[13];
    const float* bi      = (const float*)d_in[14];
    const float* Wh      = (const float*)d_in[15];
    const float* bh      = (const float*)d_in[16];
    const float* W1      = (const float*)d_in[17];
    const float* b1      = (const float*)d_in[18];
    const float* W2      = (const float*)d_in[19];
    const float* b2      = (const float*)d_in[20];
    const float* wq      = (const float*)d_in[21];
    const float* bq      = (const float*)d_in[22];
    const float* W3      = (const float*)d_in[23];
    const float* b3      = (const float*)d_in[24];
    float* out = (float*)d_out;

    // device pointers to __device__ globals (compile-time symbols ok in same TU)
    __nv_bfloat16 *p_A1s, *p_Hs, *p_intras, *p_inters, *p_Wat, *p_Uht, *p_Wit, *p_Wht;
    float *p_P, *p_Q;
    cudaGetSymbolAddress((void**)&p_A1s, g_A1s);
    cudaGetSymbolAddress((void**)&p_Hs, g_Hs);
    cudaGetSymbolAddress((void**)&p_intras, g_intras);
    cudaGetSymbolAddress((void**)&p_inters, g_inters);
    cudaGetSymbolAddress((void**)&p_Wat, g_Wat);
    cudaGetSymbolAddress((void**)&p_Uht, g_Uht);
    cudaGetSymbolAddress((void**)&p_Wit, g_Wit);
    cudaGetSymbolAddress((void**)&p_Wht, g_Wht);
    cudaGetSymbolAddress((void**)&p_P, g_P);
    cudaGetSymbolAddress((void**)&p_Q, g_Q);

    const int smemA = 14336 * 4;                 // 57344 B
    cudaFuncSetAttribute(kernelA, cudaFuncAttributeMaxDynamicSharedMemorySize, smemA);
    cudaFuncSetAttribute(gemm_split_kernel<256>,
                         cudaFuncAttributeMaxDynamicSharedMemorySize, 2 * SG_STAGE);
    cudaFuncSetAttribute(gemm_split_kernel<128>,
                         cudaFuncAttributeMaxDynamicSharedMemorySize, 2 * SG_STAGE);
    cudaFuncSetAttribute(scores_mma_kernel,
                         cudaFuncAttributeMaxDynamicSharedMemorySize, 2 * SC_STAGE);

    pack_weights_kernel<<<1008, 256>>>(W_a, U_h, Wi, Wh, W_in, W_out, W2);
    split_emb_kernel<<<(NNODE_PAD * 32) / 256, 256>>>(emb);

    kernelA<<<BB, 128, smemA>>>(items, A_in, A_out, inter, emb, b_in, b_out);

    dim3 ggrid(3, MROWS / 256);                  // 3 x 128
    gemm_split_kernel<256><<<ggrid, 512, 2 * SG_STAGE>>>(p_A1s, p_Wat, p_P);
    gemm_split_kernel<128><<<ggrid, 512, 2 * SG_STAGE>>>(p_Hs, p_Uht, p_Q);

    gates1_kernel<<<(MROWS * 128) / 256, 256>>>(b_gru);

    gemm_split_kernel<128><<<ggrid, 512, 2 * SG_STAGE>>>(p_intras, p_Wit, p_P);
    gemm_split_kernel<128><<<ggrid, 512, 2 * SG_STAGE>>>(p_inters, p_Wht, p_Q);

    gates2_kernel<<<(MROWS * 128) / 256, 256>>>(bi, bh, inter);

    readout_kernel<<<BB, 128>>>(seq_len, W1, b1, b2, wq, bq, W3, b3);

    dim3 sgrid(NNODE_PAD / 256, BB / 128);       // 196 x 8
    scores_mma_kernel<<<sgrid, 512, 2 * SC_STAGE>>>(out);
}

// round 12
// speedup vs baseline: 1.9370x; 1.0060x over previous
#include <cuda_runtime.h>
#include <cuda_bf16.h>
#include <math.h>

#define BB 1024
#define LL 32
#define DD 128
#define NNODE 50000
#define NNODE_PAD 50176   // 196 * 256
#define MROWS (BB * LL)   // 32768

typedef unsigned long long ull;

// ---------------- global scratch ----------------
__device__ __align__(16) __nv_bfloat16 g_embsplit[(size_t)NNODE_PAD * 384]; // [hi|lo|hi]
__device__ __align__(16) __nv_bfloat16 g_hssplit[BB * 384];                 // [hi|hi|lo]
__device__ __align__(16) __nv_bfloat16 g_A1s[(size_t)MROWS * 512];  // [a_in|a_out] K=256 split
__device__ __align__(16) __nv_bfloat16 g_Hs[(size_t)MROWS * 256];   // h K=128 split
__device__ __align__(16) __nv_bfloat16 g_inters[(size_t)MROWS * 256];
__device__ __align__(16) __nv_bfloat16 g_intras[(size_t)MROWS * 256];
__device__ float g_H[(size_t)MROWS * 128];
__device__ float g_P[(size_t)MROWS * 384];
__device__ float g_Q[(size_t)MROWS * 384];
__device__ float g_final[(size_t)MROWS * 128];

// weights: split-bf16 TRANSPOSED  Bw[n, k] = split(W[k, n]),  [hi(K)|lo(K)]
__device__ __align__(16) __nv_bfloat16 g_Wat[384 * 512];
__device__ __align__(16) __nv_bfloat16 g_Uht[384 * 256];
__device__ __align__(16) __nv_bfloat16 g_Wit[384 * 256];
__device__ __align__(16) __nv_bfloat16 g_Wht[384 * 256];
__device__ __align__(16) float4 g_Win_p[32 * 128];
__device__ __align__(16) float4 g_Wout_p[32 * 128];
__device__ __align__(16) float4 g_W2_p[32 * 128];

__device__ __forceinline__ float sigmoidf_(float x) { return 1.0f / (1.0f + expf(-x)); }

__device__ __forceinline__ void fma2(ull& d, ull a, ull b) {
    asm("fma.rn.f32x2 %0, %1, %2, %0;" : "+l"(d) : "l"(a), "l"(b));
}
__device__ __forceinline__ float psum(ull a) {
    float lo, hi; asm("mov.b64 {%0, %1}, %2;" : "=f"(lo), "=f"(hi) : "l"(a));
    return lo + hi;
}
__device__ __forceinline__ unsigned pkbf2(__nv_bfloat16 a, __nv_bfloat16 b) {
    __nv_bfloat162 t = __halves2bfloat162(a, b);
    return *(unsigned*)&t;
}
__device__ __forceinline__ void split_w(float w, __nv_bfloat16& hi, __nv_bfloat16& lo) {
    hi = __float2bfloat16(w);
    lo = __float2bfloat16(w - __bfloat162float(hi));
}

// ---------------------------------------------------------------------------
// Weight pack kernel
// ---------------------------------------------------------------------------
__device__ __forceinline__ void pack_one(float4* dst, const float* src, int cols, int i)
{
    int k4 = i / cols, c = i - k4 * cols;
    const float* s = src + (size_t)(k4 * 4) * cols + c;
    dst[i] = make_float4(s[0], s[cols], s[2 * cols], s[3 * cols]);
}
__device__ __forceinline__ void pack_wt(__nv_bfloat16* dst, const float* src,
                                        int K, int i)
{
    int n = i / K, k = i - n * K;
    __nv_bfloat16 hi, lo; split_w(src[(size_t)k * 384 + n], hi, lo);
    dst[(size_t)n * (2 * K) + k] = hi;
    dst[(size_t)n * (2 * K) + K + k] = lo;
}

__global__ void __launch_bounds__(256) pack_weights_kernel(
    const float* __restrict__ W_a, const float* __restrict__ U_h,
    const float* __restrict__ Wi, const float* __restrict__ Wh,
    const float* __restrict__ W_in, const float* __restrict__ W_out,
    const float* __restrict__ W2)
{
    int idx = blockIdx.x * 256 + threadIdx.x;
    if (idx < 98304)       pack_wt(g_Wat, W_a, 256, idx);
    else if (idx < 147456) pack_wt(g_Uht, U_h, 128, idx - 98304);
    else if (idx < 196608) pack_wt(g_Wit, Wi, 128, idx - 147456);
    else if (idx < 245760) pack_wt(g_Wht, Wh, 128, idx - 196608);
    else if (idx < 249856) pack_one(g_Win_p, W_in, 128, idx - 245760);
    else if (idx < 253952) pack_one(g_Wout_p, W_out, 128, idx - 249856);
    else if (idx < 258048) pack_one(g_W2_p, W2, 128, idx - 253952);
}

// ---------------------------------------------------------------------------
// emb -> split bf16 [hi | lo | hi]
// ---------------------------------------------------------------------------
__global__ void __launch_bounds__(256) split_emb_kernel(const float* __restrict__ emb)
{
    int i = blockIdx.x * 256 + threadIdx.x;
    int n = i >> 5, c4 = i & 31;
    float4 v = make_float4(0.f, 0.f, 0.f, 0.f);
    if (n < NNODE) v = *(const float4*)&emb[(size_t)n * DD + c4 * 4];
    __nv_bfloat16 h0, l0, h1, l1, h2, l2, h3, l3;
    split_w(v.x, h0, l0); split_w(v.y, h1, l1);
    split_w(v.z, h2, l2); split_w(v.w, h3, l3);
    char* row = (char*)(g_embsplit + (size_t)n * 384);
    uint2 hi = make_uint2(pkbf2(h0, h1), pkbf2(h2, h3));
    uint2 lo = make_uint2(pkbf2(l0, l1), pkbf2(l2, l3));
    *(uint2*)(row + c4 * 8)       = hi;
    *(uint2*)(row + 256 + c4 * 8) = lo;
    *(uint2*)(row + 512 + c4 * 8) = hi;
}

// ---------------------------------------------------------------------------
// f32x2 helpers for kernel A / readout
// ---------------------------------------------------------------------------
__device__ __forceinline__ void acc2wp(ull* a0, ull* a1, const float* S,
                                       const float4* __restrict__ W0p,
                                       const float4* __restrict__ W1p, int d, int l0)
{
    const ulonglong2* W0 = (const ulonglong2*)W0p;
    const ulonglong2* W1 = (const ulonglong2*)W1p;
    #pragma unroll 2
    for (int k4 = 0; k4 < 32; k4++) {
        ulonglong2 w0 = W0[k4 * 128 + d];
        ulonglong2 w1 = W1[k4 * 128 + d];
        #pragma unroll
        for (int l = 0; l < 16; l++) {
            ulonglong2 s = *(const ulonglong2*)&S[(l0 + l) * DD + k4 * 4];
            fma2(a0[l], s.x, w0.x); fma2(a0[l], s.y, w0.y);
            fma2(a1[l], s.x, w1.x); fma2(a1[l], s.y, w1.y);
        }
    }
}
__device__ __forceinline__ void acc1p(ull* a0, const float* S,
                                      const float4* __restrict__ Wp, int d)
{
    const ulonglong2* W = (const ulonglong2*)Wp;
    #pragma unroll 2
    for (int k4 = 0; k4 < 32; k4++) {
        ulonglong2 w = W[k4 * 128 + d];
        #pragma unroll
        for (int l = 0; l < LL; l++) {
            ulonglong2 s = *(const ulonglong2*)&S[l * DD + k4 * 4];
            fma2(a0[l], s.x, w.x); fma2(a0[l], s.y, w.y);
        }
    }
}

// ---------------------------------------------------------------------------
// Kernel A: embed + Win/Wout + adjacency -> split operands
// ---------------------------------------------------------------------------
__global__ void __launch_bounds__(128) kernelA(
    const int* __restrict__ items, const float* __restrict__ A_in,
    const float* __restrict__ A_out, const float* __restrict__ inter,
    const float* __restrict__ emb,
    const float* __restrict__ b_in, const float* __restrict__ b_out)
{
    extern __shared__ float sm[];
    float* H     = sm;
    float* T1    = sm + 4096;
    float* T2    = sm + 8192;
    float* sAin  = sm + 12288;
    float* sAout = sm + 13312;

    const int b = blockIdx.x;
    const int d = threadIdx.x;

    #pragma unroll 4
    for (int l = 0; l < LL; l++) {
        int idx = items[b * LL + l];
        H[l * DD + d] = emb[(size_t)idx * DD + d];
    }
    for (int i = d; i < LL * LL; i += DD) {
        sAin[i]  = A_in[b * LL * LL + i];
        sAout[i] = A_out[b * LL * LL + i];
    }
    __syncthreads();

    #pragma unroll 4
    for (int l = 0; l < LL; l++) {
        size_t row = (size_t)b * LL + l;
        float hv = H[l * DD + d];
        g_H[row * 128 + d] = hv;
        __nv_bfloat16 hi, lo; split_w(hv, hi, lo);
        g_Hs[row * 256 + d] = hi; g_Hs[row * 256 + 128 + d] = lo;
        float iv = inter[row * 128 + d];
        split_w(iv, hi, lo);
        g_inters[row * 256 + d] = hi; g_inters[row * 256 + 128 + d] = lo;
    }

    for (int h = 0; h < 2; h++) {
        const int l0 = h * 16;
        ull a0[16], a1[16];
        #pragma unroll
        for (int l = 0; l < 16; l++) { a0[l] = 0ull; a1[l] = 0ull; }
        acc2wp(a0, a1, H, g_Win_p, g_Wout_p, d, l0);
        float bv0 = b_in[d], bv1 = b_out[d];
        #pragma unroll
        for (int l = 0; l < 16; l++) {
            T1[(l0 + l) * DD + d] = psum(a0[l]) + bv0;
            T2[(l0 + l) * DD + d] = psum(a1[l]) + bv1;
        }
    }
    {
        float acc[LL];
        #pragma unroll
        for (int l = 0; l < LL; l++) acc[l] = 0.0f;
        #pragma unroll 4
        for (int m = 0; m < LL; m++) {
            float tv = T1[m * DD + d];
            #pragma unroll
            for (int l = 0; l < LL; l++) acc[l] = fmaf(sAin[l * LL + m], tv, acc[l]);
        }
        #pragma unroll
        for (int l = 0; l < LL; l++) {
            size_t row = (size_t)b * LL + l;
            __nv_bfloat16 hi, lo; split_w(acc[l], hi, lo);
            g_A1s[row * 512 + d] = hi;
            g_A1s[row * 512 + 256 + d] = lo;
        }
        #pragma unroll
        for (int l = 0; l < LL; l++) acc[l] = 0.0f;
        #pragma unroll 4
        for (int m = 0; m < LL; m++) {
            float tv = T2[m * DD + d];
            #pragma unroll
            for (int l = 0; l < LL; l++) acc[l] = fmaf(sAout[l * LL + m], tv, acc[l]);
        }
        #pragma unroll
        for (int l = 0; l < LL; l++) {
            size_t row = (size_t)b * LL + l;
            __nv_bfloat16 hi, lo; split_w(acc[l], hi, lo);
            g_A1s[row * 512 + 128 + d] = hi;
            g_A1s[row * 512 + 384 + d] = lo;
        }
    }
}

// ---------------------------------------------------------------------------
// Generic split-bf16 GEMM:  C[M,384] = A[M,K] @ W[K,384]
// 3-deep cp.async ring, one barrier per stage.
// ---------------------------------------------------------------------------
#define SG_AB (256 * 144)
#define SG_BB (128 * 144)
#define SG_STAGE (SG_AB + SG_BB)     // 55296

__device__ __forceinline__ void cp16(unsigned saddr, const void* gptr) {
    asm volatile("cp.async.cg.shared.global [%0], [%1], 16;\n" :: "r"(saddr), "l"(gptr));
}
__device__ __forceinline__ void cp_commit() { asm volatile("cp.async.commit_group;\n"); }
template<int N> __device__ __forceinline__ void cp_wait() {
    asm volatile("cp.async.wait_group %0;\n" :: "n"(N));
}
__device__ __forceinline__ void ldm4(unsigned* r, unsigned saddr) {
    asm volatile("ldmatrix.sync.aligned.m8n8.x4.shared.b16 {%0,%1,%2,%3}, [%4];"
                 : "=r"(r[0]), "=r"(r[1]), "=r"(r[2]), "=r"(r[3]) : "r"(saddr));
}
__device__ __forceinline__ void mma16816(float* c, const unsigned* a, const unsigned* b) {
    asm volatile("mma.sync.aligned.m16n8k16.row.col.f32.bf16.bf16.f32 "
                 "{%0,%1,%2,%3}, {%4,%5,%6,%7}, {%8,%9}, {%0,%1,%2,%3};"
                 : "+f"(c[0]), "+f"(c[1]), "+f"(c[2]), "+f"(c[3])
                 : "r"(a[0]), "r"(a[1]), "r"(a[2]), "r"(a[3]),
                   "r"(b[0]), "r"(b[1]));
}

template<int KK>
__global__ void __launch_bounds__(512, 1) gemm_split_kernel(
    const __nv_bfloat16* __restrict__ A, const __nv_bfloat16* __restrict__ Bw,
    float* __restrict__ C)
{
    extern __shared__ char smraw[];
    const unsigned sbase = (unsigned)__cvta_generic_to_shared(smraw);

    const int tid = threadIdx.x, lane = tid & 31, w = tid >> 5;
    const int wm = w & 7, wn = w >> 3;           // 8 M-warps x 2 N-warps (32x64)
    const int m0 = blockIdx.y * 256;
    const int n0 = blockIdx.x * 128;
    const int lr = tid >> 3, lc8 = tid & 7;

    const int NCH = KK / 64;
    const int aoffs[3] = {0, 0, KK};
    const int boffs[3] = {0, KK, 0};
    const int NS = 3 * NCH;

    auto load_stage = [&](int s) {
        int p = s / NCH, cc = s - p * NCH;
        int ga = aoffs[p] + cc * 64, gb = boffs[p] + cc * 64;
        unsigned ab = sbase + (s % 3) * SG_STAGE;
        unsigned bb = ab + SG_AB;
        #pragma unroll
        for (int i = 0; i < 4; i++) {
            int r = lr + i * 64;
            cp16(ab + r * 144 + lc8 * 16,
                 A + (size_t)(m0 + r) * (2 * KK) + ga + lc8 * 8);
        }
        #pragma unroll
        for (int i = 0; i < 2; i++) {
            int r = lr + i * 64;
            cp16(bb + r * 144 + lc8 * 16,
                 Bw + (size_t)(n0 + r) * (2 * KK) + gb + lc8 * 8);
        }
        cp_commit();
    };

    float acc[2][8][4];
    #pragma unroll
    for (int mi = 0; mi < 2; mi++)
        #pragma unroll
        for (int j = 0; j < 8; j++)
            #pragma unroll
            for (int q = 0; q < 4; q++) acc[mi][j][q] = 0.0f;

    const int a_r  = wm * 32 + (lane & 15);
    const int a_cb = ((lane >> 4) & 1) * 16;
    const int b_r  = wn * 64 + ((lane >> 4) & 1) * 8 + (lane & 7);
    const int b_cb = ((lane >> 3) & 1) * 16;

    load_stage(0);
    load_stage(1);

    for (int s = 0; s < NS; s++) {
        cp_wait<1>();
        __syncthreads();
        if (s + 2 < NS) load_stage(s + 2);

        unsigned ab = sbase + (s % 3) * SG_STAGE;
        unsigned bb = ab + SG_AB;

        #pragma unroll
        for (int kk = 0; kk < 4; kk++) {
            unsigned bfr[4][4];
            #pragma unroll
            for (int ni = 0; ni < 4; ni++)
                ldm4(bfr[ni], bb + (b_r + ni * 16) * 144 + kk * 32 + b_cb);
            #pragma unroll
            for (int mi = 0; mi < 2; mi++) {
                unsigned af[4];
                ldm4(af, ab + (a_r + mi * 16) * 144 + kk * 32 + a_cb);
                #pragma unroll
                for (int ni = 0; ni < 4; ni++) {
                    mma16816(acc[mi][2 * ni],     af, &bfr[ni][0]);
                    mma16816(acc[mi][2 * ni + 1], af, &bfr[ni][2]);
                }
            }
        }
    }

    const int r0 = m0 + wm * 32 + (lane >> 2);
    const int c0 = n0 + wn * 64 + (lane & 3) * 2;
    #pragma unroll
    for (int mi = 0; mi < 2; mi++) {
        int row = r0 + mi * 16;
        #pragma unroll
        for (int j = 0; j < 8; j++) {
            int n = c0 + j * 8;
            *(float2*)&C[(size_t)row * 384 + n] =
                make_float2(acc[mi][j][0], acc[mi][j][1]);
            *(float2*)&C[(size_t)(row + 8) * 384 + n] =
                make_float2(acc[mi][j][2], acc[mi][j][3]);
        }
    }
}

// ---------------------------------------------------------------------------
// GRU gate kernels
// ---------------------------------------------------------------------------
__global__ void __launch_bounds__(256) gates1_kernel(const float* __restrict__ b_gru)
{
    int idx = blockIdx.x * 256 + threadIdx.x;
    int row = idx >> 7, d = idx & 127;
    const float* P = g_P + (size_t)row * 384;
    const float* Q = g_Q + (size_t)row * 384;
    float r = sigmoidf_(P[d] + Q[d] + b_gru[d]);
    float z = sigmoidf_(P[128 + d] + Q[128 + d] + b_gru[128 + d]);
    float n = tanhf(P[256 + d] + b_gru[256 + d] + r * Q[256 + d]);
    float h = g_H[idx];
    float intra = (1.0f - z) * n + z * h;
    __nv_bfloat16 hi, lo; split_w(intra, hi, lo);
    g_intras[(size_t)row * 256 + d] = hi;
    g_intras[(size_t)row * 256 + 128 + d] = lo;
}

__global__ void __launch_bounds__(256) gates2_kernel(
    const float* __restrict__ bi, const float* __restrict__ bh,
    const float* __restrict__ inter)
{
    int idx = blockIdx.x * 256 + threadIdx.x;
    int row = idx >> 7, d = idx & 127;
    const float* P = g_P + (size_t)row * 384;
    const float* Q = g_Q + (size_t)row * 384;
    float r = sigmoidf_(P[d] + bi[d] + Q[d] + bh[d]);
    float z = sigmoidf_(P[128 + d] + bi[128 + d] + Q[128 + d] + bh[128 + d]);
    float n = tanhf(P[256 + d] + bi[256 + d] + r * (Q[256 + d] + bh[256 + d]));
    float iv = inter[idx];
    g_final[idx] = (1.0f - z) * n + z * iv;
}

// ---------------------------------------------------------------------------
// Readout
// ---------------------------------------------------------------------------
__global__ void __launch_bounds__(128) readout_kernel(
    const int* __restrict__ seq_len,
    const float* __restrict__ W1, const float* __restrict__ b1,
    const float* __restrict__ b2,
    const float* __restrict__ wq, const float* __restrict__ bq,
    const float* __restrict__ W3, const float* __restrict__ b3)
{
    __shared__ float Tf[LL * DD];
    __shared__ float sv[DD], ssg[DD], salpha[LL], sred[DD];

    const int b = blockIdx.x;
    const int d = threadIdx.x;
    const int warp = d >> 5, lane = d & 31;

    #pragma unroll 4
    for (int l = 0; l < LL; l++)
        Tf[l * DD + d] = g_final[((size_t)b * LL + l) * DD + d];

    const int slen = seq_len[b];
    sv[d] = Tf[(slen - 1) * DD + d];
    __syncthreads();

    float q1 = b1[d];
    #pragma unroll 4
    for (int k = 0; k < DD; k++) q1 = fmaf(sv[k], W1[k * DD + d], q1);

    float acc[LL];
    {
        ull aw[LL];
        #pragma unroll
        for (int l = 0; l < LL; l++) aw[l] = 0ull;
        acc1p(aw, Tf, g_W2_p, d);
        float bv = b2[d];
        #pragma unroll
        for (int l = 0; l < LL; l++) acc[l] = psum(aw[l]) + bv;
    }
    {
        float wqd = wq[d];
        #pragma unroll
        for (int l = 0; l < LL; l++) {
            float g = sigmoidf_(q1 + acc[l]) * wqd;
            #pragma unroll
            for (int off = 16; off > 0; off >>= 1)
                g += __shfl_xor_sync(0xffffffffu, g, off);
            if (lane == 0) sred[l * 4 + warp] = g;
        }
        __syncthreads();
        if (d < LL) {
            float a_ = sred[d * 4] + sred[d * 4 + 1] + sred[d * 4 + 2] + sred[d * 4 + 3] + bq[0];
            salpha[d] = (d < slen) ? a_ : 0.0f;
        }
        __syncthreads();
    }
    {
        float sg = 0.0f;
        #pragma unroll
        for (int l = 0; l < LL; l++) sg = fmaf(salpha[l], Tf[l * DD + d], sg);
        ssg[d] = sg;
    }
    __syncthreads();
    {
        float hs = b3[d];
        #pragma unroll 4
        for (int k = 0; k < DD; k++) hs = fmaf(sv[k], W3[k * DD + d], hs);
        #pragma unroll 4
        for (int k = 0; k < DD; k++) hs = fmaf(ssg[k], W3[(DD + k) * DD + d], hs);
        __nv_bfloat16 hi, lo; split_w(hs, hi, lo);
        __nv_bfloat16* row = g_hssplit + (size_t)b * 384;
        row[d] = hi; row[128 + d] = hi; row[256 + d] = lo;
    }
}

// ---------------------------------------------------------------------------
// Scores GEMM: tile 128x256, K=384, 512 threads, 3-deep cp.async ring
// ---------------------------------------------------------------------------
#define SC_AB (128 * 144)
#define SC_BB (256 * 144)
#define SC_STAGE (SC_AB + SC_BB)

__global__ void __launch_bounds__(512, 1) scores_mma_kernel(float* __restrict__ out)
{
    extern __shared__ char smraw[];
    const unsigned sbase = (unsigned)__cvta_generic_to_shared(smraw);

    const int tid = threadIdx.x, lane = tid & 31, w = tid >> 5;
    const int wm = w & 3, wn = w >> 2;            // 4 M x 4 N (32x64)
    const int bm0 = blockIdx.y * 128;
    const int n0  = blockIdx.x * 256;

    const __nv_bfloat16* Ag0 = g_hssplit + (size_t)bm0 * 384;
    const __nv_bfloat16* Bg0 = g_embsplit + (size_t)n0 * 384;

    const int lr = tid >> 3, lc8 = tid & 7;

    auto load_stage = [&](int s) {
        unsigned ab = sbase + (s % 3) * SC_STAGE;
        unsigned bb = ab + SC_AB;
        const __nv_bfloat16* Ag = Ag0 + s * 64;
        const __nv_bfloat16* Bg = Bg0 + s * 64;
        #pragma unroll
        for (int i = 0; i < 2; i++) {
            int r = lr + i * 64;
            cp16(ab + r * 144 + lc8 * 16, Ag + (size_t)r * 384 + lc8 * 8);
        }
        #pragma unroll
        for (int i = 0; i < 4; i++) {
            int r = lr + i * 64;
            cp16(bb + r * 144 + lc8 * 16, Bg + (size_t)r * 384 + lc8 * 8);
        }
        cp_commit();
    };

    float acc[2][8][4];
    #pragma unroll
    for (int mi = 0; mi < 2; mi++)
        #pragma unroll
        for (int j = 0; j < 8; j++)
            #pragma unroll
            for (int q = 0; q < 4; q++) acc[mi][j][q] = 0.0f;

    const int a_r  = wm * 32 + (lane & 15);
    const int a_cb = ((lane >> 4) & 1) * 16;
    const int b_r  = wn * 64 + ((lane >> 4) & 1) * 8 + (lane & 7);
    const int b_cb = ((lane >> 3) & 1) * 16;

    load_stage(0);
    load_stage(1);

    #pragma unroll
    for (int s = 0; s < 6; s++) {
        cp_wait<1>();
        __syncthreads();
        if (s + 2 < 6) load_stage(s + 2);

        unsigned ab = sbase + (s % 3) * SC_STAGE;
        unsigned bb = ab + SC_AB;

        #pragma unroll
        for (int kk = 0; kk < 4; kk++) {
            unsigned bfr[4][4];
            #pragma unroll
            for (int ni = 0; ni < 4; ni++)
                ldm4(bfr[ni], bb + (b_r + ni * 16) * 144 + kk * 32 + b_cb);
            #pragma unroll
            for (int mi = 0; mi < 2; mi++) {
                unsigned af[4];
                ldm4(af, ab + (a_r + mi * 16) * 144 + kk * 32 + a_cb);
                #pragma unroll
                for (int ni = 0; ni < 4; ni++) {
                    mma16816(acc[mi][2 * ni],     af, &bfr[ni][0]);
                    mma16816(acc[mi][2 * ni + 1], af, &bfr[ni][2]);
                }
            }
        }
    }

    const int r0 = bm0 + wm * 32 + (lane >> 2);
    const int c0 = n0 + wn * 64 + (lane & 3) * 2;
    #pragma unroll
    for (int mi = 0; mi < 2; mi++) {
        int row = r0 + mi * 16;
        #pragma unroll
        for (int j = 0; j < 8; j++) {
            int n = c0 + j * 8;
            if (n < NNODE) {
                *(float2*)&out[(size_t)row * NNODE + n] =
                    make_float2(acc[mi][j][0], acc[mi][j][1]);
                *(float2*)&out[(size_t)(row + 8) * NNODE + n] =
                    make_float2(acc[mi][j][2], acc[mi][j][3]);
            }
        }
    }
}

// ---------------------------------------------------------------------------
extern "C" void kernel_launch(void* const* d_in, const int* in_sizes, int n_in,
                              void* d_out, int out_size)
{
    (void)in_sizes; (void)n_in; (void)out_size;
    const int*   items   = (const int*)d_in[0];
    const float* A_in    = (const float*)d_in[1];
    const float* A_out   = (const float*)d_in[2];
    const float* inter   = (const float*)d_in[3];
    const int*   seq_len = (const int*)d_in[4];
    const float* emb     = (const float*)d_in[5];
    const float* W_in    = (const float*)d_in[6];
    const float* b_in    = (const float*)d_in[7];
    const float* W_out   = (const float*)d_in[8];
    const float* b_out   = (const float*)d_in[9];
    const float* W_a     = (const float*)d_in[10];
    const float* U_h     = (const float*)d_in[11];
    const float* b_gru   = (const float*)d_in[12];
    const float* Wi      = (const float*)d_in[13];
    const float* bi      = (const float*)d_in[14];
    const float* Wh      = (const float*)d_in[15];
    const float* bh      = (const float*)d_in[16];
    const float* W1      = (const float*)d_in[17];
    const float* b1      = (const float*)d_in[18];
    const float* W2      = (const float*)d_in[19];
    const float* b2      = (const float*)d_in[20];
    const float* wq      = (const float*)d_in[21];
    const float* bq      = (const float*)d_in[22];
    const float* W3      = (const float*)d_in[23];
    const float* b3      = (const float*)d_in[24];
    float* out = (float*)d_out;

    __nv_bfloat16 *p_A1s, *p_Hs, *p_intras, *p_inters, *p_Wat, *p_Uht, *p_Wit, *p_Wht;
    float *p_P, *p_Q;
    cudaGetSymbolAddress((void**)&p_A1s, g_A1s);
    cudaGetSymbolAddress((void**)&p_Hs, g_Hs);
    cudaGetSymbolAddress((void**)&p_intras, g_intras);
    cudaGetSymbolAddress((void**)&p_inters, g_inters);
    cudaGetSymbolAddress((void**)&p_Wat, g_Wat);
    cudaGetSymbolAddress((void**)&p_Uht, g_Uht);
    cudaGetSymbolAddress((void**)&p_Wit, g_Wit);
    cudaGetSymbolAddress((void**)&p_Wht, g_Wht);
    cudaGetSymbolAddress((void**)&p_P, g_P);
    cudaGetSymbolAddress((void**)&p_Q, g_Q);

    const int smemA = 14336 * 4;
    cudaFuncSetAttribute(kernelA, cudaFuncAttributeMaxDynamicSharedMemorySize, smemA);
    cudaFuncSetAttribute(gemm_split_kernel<256>,
                         cudaFuncAttributeMaxDynamicSharedMemorySize, 3 * SG_STAGE);
    cudaFuncSetAttribute(gemm_split_kernel<128>,
                         cudaFuncAttributeMaxDynamicSharedMemorySize, 3 * SG_STAGE);
    cudaFuncSetAttribute(scores_mma_kernel,
                         cudaFuncAttributeMaxDynamicSharedMemorySize, 3 * SC_STAGE);

    pack_weights_kernel<<<1008, 256>>>(W_a, U_h, Wi, Wh, W_in, W_out, W2);
    split_emb_kernel<<<(NNODE_PAD * 32) / 256, 256>>>(emb);

    kernelA<<<BB, 128, smemA>>>(items, A_in, A_out, inter, emb, b_in, b_out);

    dim3 ggrid(3, MROWS / 256);
    gemm_split_kernel<256><<<ggrid, 512, 3 * SG_STAGE>>>(p_A1s, p_Wat, p_P);
    gemm_split_kernel<128><<<ggrid, 512, 3 * SG_STAGE>>>(p_Hs, p_Uht, p_Q);

    gates1_kernel<<<(MROWS * 128) / 256, 256>>>(b_gru);

    gemm_split_kernel<128><<<ggrid, 512, 3 * SG_STAGE>>>(p_intras, p_Wit, p_P);
    gemm_split_kernel<128><<<ggrid, 512, 3 * SG_STAGE>>>(p_inters, p_Wht, p_Q);

    gates2_kernel<<<(MROWS * 128) / 256, 256>>>(bi, bh, inter);

    readout_kernel<<<BB, 128>>>(seq_len, W1, b1, b2, wq, bq, W3, b3);

    dim3 sgrid(NNODE_PAD / 256, BB / 128);
    scores_mma_kernel<<<sgrid, 512, 3 * SC_STAGE>>>(out);
}